// round 2
// baseline (speedup 1.0000x reference)
#include <cuda_runtime.h>
#include <cuda_bf16.h>
#include <cfloat>
#include <math.h>

// Problem constants
#define B_   8
#define N_   4096
#define M_   64
#define DIM_ 1024
#define H_   16
#define DH_  64
#define INNER_ 1024      // H_*DH_
#define KV2_  2048       // 2*INNER_

// ---------------- scratch (device globals; no allocation allowed) ----------
__device__ float g_q[B_ * M_ * INNER_];                 // (b*m, inner), pre-scaled by DH^-0.5
__device__ float g_kv[(size_t)B_ * N_ * KV2_];          // (b*n, 2048): [0,1024)=k, [1024,2048)=v
__device__ float g_sim[(size_t)B_ * H_ * M_ * N_];      // (bh*64 + i, n)
__device__ float g_rmax[B_ * H_ * M_];                  // per (bh,i) row max
__device__ float g_attnout[B_ * M_ * INNER_];           // (b*m, inner) final layout for out proj
__device__ float g_losspart[2048];                      // per-block loss partials

// ---------------- generic fp32 GEMM: C[MxN] = alpha * A[MxK] * B[NxK]^T ----
// Both A and B row-major with K contiguous. 128x128 block tile, 8x8 per thread.
__global__ __launch_bounds__(256) void gemm_nt_kernel(
    const float* __restrict__ A, const float* __restrict__ Bm,
    float* __restrict__ C, int M, int N, int K, float alpha)
{
    __shared__ float As[16][128];
    __shared__ float Bs[16][128];
    const int tid  = threadIdx.x;
    const int row0 = blockIdx.y * 128;
    const int col0 = blockIdx.x * 128;
    const int tr = tid >> 4;   // 0..15
    const int tc = tid & 15;   // 0..15

    float acc[8][8];
#pragma unroll
    for (int i = 0; i < 8; i++)
#pragma unroll
        for (int j = 0; j < 8; j++) acc[i][j] = 0.f;

    for (int k0 = 0; k0 < K; k0 += 16) {
#pragma unroll
        for (int s = tid; s < 512; s += 256) {
            int m  = s >> 2;
            int kq = (s & 3) * 4;
            float4 va = *reinterpret_cast<const float4*>(&A[(size_t)(row0 + m) * K + k0 + kq]);
            As[kq + 0][m] = va.x; As[kq + 1][m] = va.y;
            As[kq + 2][m] = va.z; As[kq + 3][m] = va.w;
            float4 vb = *reinterpret_cast<const float4*>(&Bm[(size_t)(col0 + m) * K + k0 + kq]);
            Bs[kq + 0][m] = vb.x; Bs[kq + 1][m] = vb.y;
            Bs[kq + 2][m] = vb.z; Bs[kq + 3][m] = vb.w;
        }
        __syncthreads();
#pragma unroll
        for (int k = 0; k < 16; k++) {
            float a[8], b[8];
#pragma unroll
            for (int i = 0; i < 8; i++) a[i] = As[k][tr * 8 + i];
#pragma unroll
            for (int j = 0; j < 8; j++) b[j] = Bs[k][tc * 8 + j];
#pragma unroll
            for (int i = 0; i < 8; i++)
#pragma unroll
                for (int j = 0; j < 8; j++) acc[i][j] += a[i] * b[j];
        }
        __syncthreads();
    }
#pragma unroll
    for (int i = 0; i < 8; i++) {
        size_t base = (size_t)(row0 + tr * 8 + i) * N + col0 + tc * 8;
#pragma unroll
        for (int j = 0; j < 8; j++) C[base + j] = alpha * acc[i][j];
    }
}

// ---------------- K3: sim[bh, i, n] = q_i . k_n (masked -> -FLT_MAX) -------
// mask is int32 (bool upcast by harness): nonzero = masked out
__global__ __launch_bounds__(256) void sim_kernel(const int* __restrict__ mask)
{
    const int bh = blockIdx.y;          // 0..127
    const int b  = bh >> 4;
    const int h  = bh & 15;
    const int n0 = blockIdx.x * 64;
    const int tid = threadIdx.x;

    __shared__ float qs[64][65];
    __shared__ float ks[64][65];

    for (int s = tid; s < 4096; s += 256) {
        int r = s >> 6, d = s & 63;
        qs[r][d] = g_q[(size_t)(b * M_ + r) * INNER_ + h * DH_ + d];
        ks[r][d] = g_kv[((size_t)b * N_ + n0 + r) * KV2_ + h * DH_ + d];
    }
    __syncthreads();

    const int ty = tid >> 4, tx = tid & 15;
    float acc[4][4];
#pragma unroll
    for (int u = 0; u < 4; u++)
#pragma unroll
        for (int v = 0; v < 4; v++) acc[u][v] = 0.f;

#pragma unroll 8
    for (int d = 0; d < 64; d++) {
        float a[4], c[4];
#pragma unroll
        for (int u = 0; u < 4; u++) a[u] = qs[ty + 16 * u][d];
#pragma unroll
        for (int v = 0; v < 4; v++) c[v] = ks[tx + 16 * v][d];
#pragma unroll
        for (int u = 0; u < 4; u++)
#pragma unroll
            for (int v = 0; v < 4; v++) acc[u][v] += a[u] * c[v];
    }

#pragma unroll
    for (int u = 0; u < 4; u++) {
        int i = ty + 16 * u;
#pragma unroll
        for (int v = 0; v < 4; v++) {
            int n = n0 + tx + 16 * v;
            float val = (mask[b * N_ + n] != 0) ? -FLT_MAX : acc[u][v];
            g_sim[((size_t)bh * M_ + i) * N_ + n] = val;
        }
    }
}

// ---------------- K4: row max over n -------------------------------------
__global__ __launch_bounds__(256) void rowmax_kernel()
{
    const int row = blockIdx.x;          // 0 .. B*H*M-1
    const float* p = &g_sim[(size_t)row * N_];
    float m = -FLT_MAX;
    for (int j = threadIdx.x; j < N_; j += 256) m = fmaxf(m, p[j]);
    __shared__ float red[256];
    red[threadIdx.x] = m;
    __syncthreads();
    for (int s = 128; s > 0; s >>= 1) {
        if (threadIdx.x < s) red[threadIdx.x] = fmaxf(red[threadIdx.x], red[threadIdx.x + s]);
        __syncthreads();
    }
    if (threadIdx.x == 0) g_rmax[row] = red[0];
}

// ---------------- K5: per-column variance -> loss partials ----------------
__global__ __launch_bounds__(256) void colstat_kernel(const int* __restrict__ mask)
{
    const int g0 = blockIdx.x * 256;
    const int bh = g0 / N_;              // constant per block (256 | 4096)
    const int b  = bh >> 4;
    const int j  = (g0 % N_) + threadIdx.x;

    __shared__ float rs[64];
    if (threadIdx.x < 64) rs[threadIdx.x] = g_rmax[bh * M_ + threadIdx.x];
    __syncthreads();

    float contrib = 0.f;
    if (mask[b * N_ + j] == 0) {
        float s = 0.f, ss = 0.f;
#pragma unroll 8
        for (int i = 0; i < 64; i++) {
            float v = g_sim[((size_t)bh * M_ + i) * N_ + j] - rs[i];
            s += v; ss += v * v;
        }
        float var = (ss - s * s * (1.0f / 64.f)) * (1.0f / 63.f);
        float sd  = sqrtf(var + 1e-4f);
        contrib = fmaxf(1.0f - sd, 0.0f);
    }
    __shared__ float red[256];
    red[threadIdx.x] = contrib;
    __syncthreads();
    for (int s = 128; s > 0; s >>= 1) {
        if (threadIdx.x < s) red[threadIdx.x] += red[threadIdx.x + s];
        __syncthreads();
    }
    if (threadIdx.x == 0) g_losspart[blockIdx.x] = red[0];
}

__global__ __launch_bounds__(256) void loss_final_kernel(float* __restrict__ out, int idx)
{
    float s = 0.f;
    for (int i = threadIdx.x; i < 2048; i += 256) s += g_losspart[i];
    __shared__ float red[256];
    red[threadIdx.x] = s;
    __syncthreads();
    for (int t = 128; t > 0; t >>= 1) {
        if (threadIdx.x < t) red[threadIdx.x] += red[threadIdx.x + t];
        __syncthreads();
    }
    if (threadIdx.x == 0) out[idx] = red[0] * (1.0f / (float)(B_ * H_ * N_));
}

// ---------------- K6: softmax + attn@V per (b,h) --------------------------
__global__ __launch_bounds__(256) void pv_kernel()
{
    const int bh = blockIdx.x;
    const int b  = bh >> 4;
    const int h  = bh & 15;
    const int tid = threadIdx.x;

    __shared__ float ps[64][65];
    __shared__ float vs[64][65];
    __shared__ float denom[64];
    __shared__ float rs[64];

    if (tid < 64) { denom[tid] = 0.f; rs[tid] = g_rmax[bh * M_ + tid]; }
    __syncthreads();

    const int ty = tid >> 4, tx = tid & 15;
    float acc[4][4];
#pragma unroll
    for (int u = 0; u < 4; u++)
#pragma unroll
        for (int c = 0; c < 4; c++) acc[u][c] = 0.f;

    for (int jt = 0; jt < 64; jt++) {
        const int j0 = jt * 64;
        for (int s = tid; s < 4096; s += 256) {
            int r = s >> 6, d = s & 63;
            vs[r][d] = g_kv[((size_t)b * N_ + j0 + r) * KV2_ + INNER_ + h * DH_ + d];
            ps[r][d] = expf(g_sim[((size_t)bh * M_ + r) * N_ + j0 + d] - rs[r]);
        }
        __syncthreads();
        if (tid < 64) {
            float s = 0.f;
#pragma unroll 8
            for (int j = 0; j < 64; j++) s += ps[tid][j];
            denom[tid] += s;
        }
#pragma unroll 4
        for (int j = 0; j < 64; j++) {
            float pv[4], vv[4];
#pragma unroll
            for (int u = 0; u < 4; u++) pv[u] = ps[ty + 16 * u][j];
#pragma unroll
            for (int c = 0; c < 4; c++) vv[c] = vs[j][tx + 16 * c];
#pragma unroll
            for (int u = 0; u < 4; u++)
#pragma unroll
                for (int c = 0; c < 4; c++) acc[u][c] += pv[u] * vv[c];
        }
        __syncthreads();
    }

#pragma unroll
    for (int u = 0; u < 4; u++) {
        int i = ty + 16 * u;
        float inv = 1.0f / denom[i];
#pragma unroll
        for (int c = 0; c < 4; c++) {
            int d = tx + 16 * c;
            g_attnout[((size_t)b * M_ + i) * INNER_ + h * DH_ + d] = acc[u][c] * inv;
        }
    }
}

// ---------------- launch ---------------------------------------------------
extern "C" void kernel_launch(void* const* d_in, const int* in_sizes, int n_in,
                              void* d_out, int out_size)
{
    const float* x       = (const float*)d_in[0];
    const float* latents = (const float*)d_in[1];
    const int*   mask    = (const int*)d_in[2];
    const float* Wq      = (const float*)d_in[3];
    const float* Wkv     = (const float*)d_in[4];
    const float* Wout    = (const float*)d_in[5];
    float*       out     = (float*)d_out;

    void *pq, *pkv, *pattn;
    cudaGetSymbolAddress(&pq, g_q);
    cudaGetSymbolAddress(&pkv, g_kv);
    cudaGetSymbolAddress(&pattn, g_attnout);

    const float scale = 0.125f;  // DH^-0.5

    // K1: q = latents @ Wq^T * scale   (M=512, N=1024, K=1024)
    gemm_nt_kernel<<<dim3(INNER_ / 128, (B_ * M_) / 128), 256>>>(
        latents, Wq, (float*)pq, B_ * M_, INNER_, DIM_, scale);

    // K2: kv = x @ Wkv^T               (M=32768, N=2048, K=1024)
    gemm_nt_kernel<<<dim3(KV2_ / 128, (B_ * N_) / 128), 256>>>(
        x, Wkv, (float*)pkv, B_ * N_, KV2_, DIM_, 1.0f);

    // K3: sim + mask
    sim_kernel<<<dim3(N_ / 64, B_ * H_), 256>>>(mask);

    // K4: row max
    rowmax_kernel<<<B_ * H_ * M_, 256>>>();

    // K5: variance loss partials + finalize
    colstat_kernel<<<(B_ * H_ * N_) / 256, 256>>>(mask);
    loss_final_kernel<<<1, 256>>>(out, out_size - 1);

    // K6: softmax + attn @ V
    pv_kernel<<<B_ * H_, 256>>>();

    // K7: out = attn_out @ Wout^T -> d_out (M=512, N=1024, K=1024)
    gemm_nt_kernel<<<dim3(DIM_ / 128, (B_ * M_) / 128), 256>>>(
        (const float*)pattn, Wout, out, B_ * M_, DIM_, INNER_, 1.0f);
}

// round 4
// speedup vs baseline: 1.8385x; 1.8385x over previous
#include <cuda_runtime.h>
#include <cuda_bf16.h>
#include <cfloat>
#include <math.h>
#include <cstdint>

// Problem constants
#define B_   8
#define N_   4096
#define M_   64
#define DIM_ 1024
#define H_   16
#define DH_  64
#define INNER_ 1024
#define KV2_  2048

// ==================== scratch (device globals) =============================
__device__ float g_q[B_ * M_ * INNER_];
__device__ float g_kv[(size_t)B_ * N_ * KV2_];
__device__ float g_sim[(size_t)B_ * H_ * M_ * N_];
__device__ float g_rmax[B_ * H_ * M_];
__device__ float g_attnout[B_ * M_ * INNER_];
__device__ float g_losspart[2048];

// ==================== helpers =============================================
__device__ __forceinline__ uint32_t smem_u32(const void* p) {
    uint32_t a;
    asm("{ .reg .u64 t; cvta.to.shared.u64 t, %1; cvt.u32.u64 %0, t; }" : "=r"(a) : "l"(p));
    return a;
}
__device__ __forceinline__ uint32_t lds32(uint32_t a) {
    uint32_t v;
    asm volatile("ld.shared.b32 %0, [%1];" : "=r"(v) : "r"(a));
    return v;
}
#define LDMX4(r, addr) \
    asm volatile("ldmatrix.sync.aligned.m8n8.x4.shared.b16 {%0,%1,%2,%3}, [%4];" \
        : "=r"((r)[0]), "=r"((r)[1]), "=r"((r)[2]), "=r"((r)[3]) : "r"(addr))
#define MMA_BF16(c, a, b) \
    asm volatile("mma.sync.aligned.m16n8k16.row.col.f32.bf16.bf16.f32 " \
        "{%0,%1,%2,%3}, {%4,%5,%6,%7}, {%8,%9}, {%0,%1,%2,%3};" \
        : "+f"((c)[0]), "+f"((c)[1]), "+f"((c)[2]), "+f"((c)[3]) \
        : "r"((a)[0]), "r"((a)[1]), "r"((a)[2]), "r"((a)[3]), "r"((b)[0]), "r"((b)[1]))

__device__ __forceinline__ uint2 hi_pack(float4 v) {
    __nv_bfloat162 p0(__float2bfloat16(v.x), __float2bfloat16(v.y));
    __nv_bfloat162 p1(__float2bfloat16(v.z), __float2bfloat16(v.w));
    uint2 r;
    r.x = *reinterpret_cast<uint32_t*>(&p0);
    r.y = *reinterpret_cast<uint32_t*>(&p1);
    return r;
}
__device__ __forceinline__ uint2 lo_pack(float4 v) {
    float4 l;
    l.x = v.x - __bfloat162float(__float2bfloat16(v.x));
    l.y = v.y - __bfloat162float(__float2bfloat16(v.y));
    l.z = v.z - __bfloat162float(__float2bfloat16(v.z));
    l.w = v.w - __bfloat162float(__float2bfloat16(v.w));
    return hi_pack(l);
}

// ==================== bf16-split GEMM via mma.sync =========================
// C[Mg x Ng] = alpha * A * B^T; A: Mg x Kg fp32, B: Ng x Kg fp32, K-contiguous.
// Split precision: acc += Ahi*Bhi + Ahi*Blo + Alo*Bhi (fp32 mma accumulators).
// Tile 128x128, BK=32, 8 warps (2x4), warp tile 64x32, double-buffered smem.
// Smem per stage: 4 tiles (Ahi,Alo,Bhi,Blo), each 128 rows x 40 bf16 (80B rows).
#define TILE_BYTES   10240      // 128*40*2
#define STAGE_BYTES  40960      // 4 tiles
#define GSMEM_BYTES  81920      // 2 stages

__global__ __launch_bounds__(256, 1) void gemm_mma_kernel(
    const float* __restrict__ A, const float* __restrict__ Bm, float* __restrict__ C,
    int Ng, int Kg, float alpha)
{
    extern __shared__ char sm[];
    const uint32_t smb = smem_u32(sm);
    const int tid  = threadIdx.x;
    const int lane = tid & 31;
    const int wid  = tid >> 5;
    const int wm   = wid >> 2;        // 0..1
    const int wn   = wid & 3;         // 0..3
    const int row0 = blockIdx.y * 128;
    const int col0 = blockIdx.x * 128;

    float acc[4][4][4];
#pragma unroll
    for (int mt = 0; mt < 4; mt++)
#pragma unroll
        for (int nt = 0; nt < 4; nt++)
#pragma unroll
            for (int e = 0; e < 4; e++) acc[mt][nt][e] = 0.f;

    float4 ra[4], rb[4];
    const int rr = tid >> 3;   // 0..31
    const int cc = tid & 7;    // float4 index within 32-float row chunk

#define LDG_TILES(k0) do { \
    _Pragma("unroll") \
    for (int i = 0; i < 4; i++) { \
        ra[i] = *reinterpret_cast<const float4*>(&A[(size_t)(row0 + rr + i * 32) * Kg + (k0) + cc * 4]); \
        rb[i] = *reinterpret_cast<const float4*>(&Bm[(size_t)(col0 + rr + i * 32) * Kg + (k0) + cc * 4]); \
    } } while (0)

#define STS_TILES(s) do { \
    char* sbp = sm + (s) * STAGE_BYTES; \
    _Pragma("unroll") \
    for (int i = 0; i < 4; i++) { \
        int off = (rr + i * 32) * 80 + cc * 8; \
        *reinterpret_cast<uint2*>(sbp + off)                  = hi_pack(ra[i]); \
        *reinterpret_cast<uint2*>(sbp + TILE_BYTES + off)     = lo_pack(ra[i]); \
        *reinterpret_cast<uint2*>(sbp + 2 * TILE_BYTES + off) = hi_pack(rb[i]); \
        *reinterpret_cast<uint2*>(sbp + 3 * TILE_BYTES + off) = lo_pack(rb[i]); \
    } } while (0)

#define COMPUTE(s) do { \
    uint32_t sb = smb + (s) * STAGE_BYTES; \
    _Pragma("unroll") \
    for (int ks = 0; ks < 2; ks++) { \
        uint32_t ah[4][4], al[4][4], bh[4][2], bl[4][2]; \
        _Pragma("unroll") \
        for (int mt = 0; mt < 4; mt++) { \
            uint32_t ad = sb + (uint32_t)(wm * 64 + mt * 16 + (lane & 15)) * 80 \
                          + ks * 32 + (lane >> 4) * 16; \
            LDMX4(ah[mt], ad); \
            LDMX4(al[mt], ad + TILE_BYTES); \
        } \
        _Pragma("unroll") \
        for (int nt = 0; nt < 4; nt++) { \
            uint32_t bd = sb + 2 * TILE_BYTES \
                          + (uint32_t)(wn * 32 + nt * 8 + (lane >> 2)) * 80 \
                          + (lane & 3) * 4 + ks * 32; \
            bh[nt][0] = lds32(bd);      bh[nt][1] = lds32(bd + 16); \
            bl[nt][0] = lds32(bd + TILE_BYTES); bl[nt][1] = lds32(bd + TILE_BYTES + 16); \
        } \
        _Pragma("unroll") \
        for (int mt = 0; mt < 4; mt++) \
        _Pragma("unroll") \
        for (int nt = 0; nt < 4; nt++) { \
            MMA_BF16(acc[mt][nt], ah[mt], bh[nt]); \
            MMA_BF16(acc[mt][nt], ah[mt], bl[nt]); \
            MMA_BF16(acc[mt][nt], al[mt], bh[nt]); \
        } \
    } } while (0)

    LDG_TILES(0);
    STS_TILES(0);
    __syncthreads();

    const int nk = Kg >> 5;
    for (int k = 0; k < nk; k++) {
        if (k + 1 < nk) LDG_TILES((k + 1) * 32);
        COMPUTE(k & 1);
        if (k + 1 < nk) STS_TILES((k + 1) & 1);
        __syncthreads();
    }

    // epilogue: c0,c1 at row g, cols 2*(lane&3)+{0,1}; c2,c3 at row g+8
#pragma unroll
    for (int mt = 0; mt < 4; mt++) {
        int r = row0 + wm * 64 + mt * 16 + (lane >> 2);
#pragma unroll
        for (int nt = 0; nt < 4; nt++) {
            int c = col0 + wn * 32 + nt * 8 + (lane & 3) * 2;
            float2 v0 = make_float2(alpha * acc[mt][nt][0], alpha * acc[mt][nt][1]);
            float2 v1 = make_float2(alpha * acc[mt][nt][2], alpha * acc[mt][nt][3]);
            *reinterpret_cast<float2*>(&C[(size_t)r * Ng + c]) = v0;
            *reinterpret_cast<float2*>(&C[(size_t)(r + 8) * Ng + c]) = v1;
        }
    }
#undef LDG_TILES
#undef STS_TILES
#undef COMPUTE
}

// ==================== K3: sim + mask ======================================
__global__ __launch_bounds__(256) void sim_kernel(const int* __restrict__ mask)
{
    const int bh = blockIdx.y;
    const int b  = bh >> 4;
    const int h  = bh & 15;
    const int n0 = blockIdx.x * 64;
    const int tid = threadIdx.x;

    __shared__ float qs[64][65];
    __shared__ float ks[64][65];

    for (int s = tid; s < 4096; s += 256) {
        int r = s >> 6, d = s & 63;
        qs[r][d] = g_q[(size_t)(b * M_ + r) * INNER_ + h * DH_ + d];
        ks[r][d] = g_kv[((size_t)b * N_ + n0 + r) * KV2_ + h * DH_ + d];
    }
    __syncthreads();

    const int ty = tid >> 4, tx = tid & 15;
    float acc[4][4];
#pragma unroll
    for (int u = 0; u < 4; u++)
#pragma unroll
        for (int v = 0; v < 4; v++) acc[u][v] = 0.f;

#pragma unroll 8
    for (int d = 0; d < 64; d++) {
        float a[4], c[4];
#pragma unroll
        for (int u = 0; u < 4; u++) a[u] = qs[ty + 16 * u][d];
#pragma unroll
        for (int v = 0; v < 4; v++) c[v] = ks[tx + 16 * v][d];
#pragma unroll
        for (int u = 0; u < 4; u++)
#pragma unroll
            for (int v = 0; v < 4; v++) acc[u][v] += a[u] * c[v];
    }

#pragma unroll
    for (int u = 0; u < 4; u++) {
        int i = ty + 16 * u;
#pragma unroll
        for (int v = 0; v < 4; v++) {
            int n = n0 + tx + 16 * v;
            float val = (mask[b * N_ + n] != 0) ? -FLT_MAX : acc[u][v];
            g_sim[((size_t)bh * M_ + i) * N_ + n] = val;
        }
    }
}

// ==================== K4: row max =========================================
__global__ __launch_bounds__(256) void rowmax_kernel()
{
    const int row = blockIdx.x;
    const float* p = &g_sim[(size_t)row * N_];
    float m = -FLT_MAX;
    for (int j = threadIdx.x; j < N_; j += 256) m = fmaxf(m, p[j]);
    __shared__ float red[256];
    red[threadIdx.x] = m;
    __syncthreads();
    for (int s = 128; s > 0; s >>= 1) {
        if (threadIdx.x < s) red[threadIdx.x] = fmaxf(red[threadIdx.x], red[threadIdx.x + s]);
        __syncthreads();
    }
    if (threadIdx.x == 0) g_rmax[row] = red[0];
}

// ==================== K5: variance loss ===================================
__global__ __launch_bounds__(256) void colstat_kernel(const int* __restrict__ mask)
{
    const int g0 = blockIdx.x * 256;
    const int bh = g0 / N_;
    const int b  = bh >> 4;
    const int j  = (g0 % N_) + threadIdx.x;

    __shared__ float rs[64];
    if (threadIdx.x < 64) rs[threadIdx.x] = g_rmax[bh * M_ + threadIdx.x];
    __syncthreads();

    float contrib = 0.f;
    if (mask[b * N_ + j] == 0) {
        float s = 0.f, ss = 0.f;
#pragma unroll 8
        for (int i = 0; i < 64; i++) {
            float v = g_sim[((size_t)bh * M_ + i) * N_ + j] - rs[i];
            s += v; ss += v * v;
        }
        float var = (ss - s * s * (1.0f / 64.f)) * (1.0f / 63.f);
        float sd  = sqrtf(var + 1e-4f);
        contrib = fmaxf(1.0f - sd, 0.0f);
    }
    __shared__ float red[256];
    red[threadIdx.x] = contrib;
    __syncthreads();
    for (int s = 128; s > 0; s >>= 1) {
        if (threadIdx.x < s) red[threadIdx.x] += red[threadIdx.x + s];
        __syncthreads();
    }
    if (threadIdx.x == 0) g_losspart[blockIdx.x] = red[0];
}

__global__ __launch_bounds__(256) void loss_final_kernel(float* __restrict__ out, int idx)
{
    float s = 0.f;
    for (int i = threadIdx.x; i < 2048; i += 256) s += g_losspart[i];
    __shared__ float red[256];
    red[threadIdx.x] = s;
    __syncthreads();
    for (int t = 128; t > 0; t >>= 1) {
        if (threadIdx.x < t) red[threadIdx.x] += red[threadIdx.x + t];
        __syncthreads();
    }
    if (threadIdx.x == 0) out[idx] = red[0] * (1.0f / (float)(B_ * H_ * N_));
}

// ==================== K6: softmax + attn@V ================================
__global__ __launch_bounds__(256) void pv_kernel()
{
    const int bh = blockIdx.x;
    const int b  = bh >> 4;
    const int h  = bh & 15;
    const int tid = threadIdx.x;

    __shared__ float ps[64][65];
    __shared__ float vs[64][65];
    __shared__ float denom[64];
    __shared__ float rs[64];

    if (tid < 64) { denom[tid] = 0.f; rs[tid] = g_rmax[bh * M_ + tid]; }
    __syncthreads();

    const int ty = tid >> 4, tx = tid & 15;
    float acc[4][4];
#pragma unroll
    for (int u = 0; u < 4; u++)
#pragma unroll
        for (int c = 0; c < 4; c++) acc[u][c] = 0.f;

    for (int jt = 0; jt < 64; jt++) {
        const int j0 = jt * 64;
        for (int s = tid; s < 4096; s += 256) {
            int r = s >> 6, d = s & 63;
            vs[r][d] = g_kv[((size_t)b * N_ + j0 + r) * KV2_ + INNER_ + h * DH_ + d];
            ps[r][d] = expf(g_sim[((size_t)bh * M_ + r) * N_ + j0 + d] - rs[r]);
        }
        __syncthreads();
        if (tid < 64) {
            float s = 0.f;
#pragma unroll 8
            for (int j = 0; j < 64; j++) s += ps[tid][j];
            denom[tid] += s;
        }
#pragma unroll 4
        for (int j = 0; j < 64; j++) {
            float pv[4], vv[4];
#pragma unroll
            for (int u = 0; u < 4; u++) pv[u] = ps[ty + 16 * u][j];
#pragma unroll
            for (int c = 0; c < 4; c++) vv[c] = vs[j][tx + 16 * c];
#pragma unroll
            for (int u = 0; u < 4; u++)
#pragma unroll
                for (int c = 0; c < 4; c++) acc[u][c] += pv[u] * vv[c];
        }
        __syncthreads();
    }

#pragma unroll
    for (int u = 0; u < 4; u++) {
        int i = ty + 16 * u;
        float inv = 1.0f / denom[i];
#pragma unroll
        for (int c = 0; c < 4; c++) {
            int d = tx + 16 * c;
            g_attnout[((size_t)b * M_ + i) * INNER_ + h * DH_ + d] = acc[u][c] * inv;
        }
    }
}

// ==================== launch ==============================================
extern "C" void kernel_launch(void* const* d_in, const int* in_sizes, int n_in,
                              void* d_out, int out_size)
{
    const float* x       = (const float*)d_in[0];
    const float* latents = (const float*)d_in[1];
    const int*   mask    = (const int*)d_in[2];
    const float* Wq      = (const float*)d_in[3];
    const float* Wkv     = (const float*)d_in[4];
    const float* Wout    = (const float*)d_in[5];
    float*       out     = (float*)d_out;

    cudaFuncSetAttribute(gemm_mma_kernel, cudaFuncAttributeMaxDynamicSharedMemorySize, GSMEM_BYTES);

    void *pq, *pkv, *pattn;
    cudaGetSymbolAddress(&pq, g_q);
    cudaGetSymbolAddress(&pkv, g_kv);
    cudaGetSymbolAddress(&pattn, g_attnout);

    // K1: q = latents @ Wq^T * scale   (512 x 1024, K=1024)
    gemm_mma_kernel<<<dim3(INNER_ / 128, (B_ * M_) / 128), 256, GSMEM_BYTES>>>(
        latents, Wq, (float*)pq, INNER_, DIM_, 0.125f);

    // K2: kv = x @ Wkv^T               (32768 x 2048, K=1024)
    gemm_mma_kernel<<<dim3(KV2_ / 128, (B_ * N_) / 128), 256, GSMEM_BYTES>>>(
        x, Wkv, (float*)pkv, KV2_, DIM_, 1.0f);

    // K3: sim + mask
    sim_kernel<<<dim3(N_ / 64, B_ * H_), 256>>>(mask);

    // K4: row max
    rowmax_kernel<<<B_ * H_ * M_, 256>>>();

    // K5: variance loss
    colstat_kernel<<<(B_ * H_ * N_) / 256, 256>>>(mask);
    loss_final_kernel<<<1, 256>>>(out, out_size - 1);

    // K6: softmax + attn@V
    pv_kernel<<<B_ * H_, 256>>>();

    // K7: out = attn_out @ Wout^T      (512 x 1024, K=1024)
    gemm_mma_kernel<<<dim3(DIM_ / 128, (B_ * M_) / 128), 256, GSMEM_BYTES>>>(
        (const float*)pattn, Wout, out, DIM_, INNER_, 1.0f);
}

// round 5
// speedup vs baseline: 3.0229x; 1.6443x over previous
#include <cuda_runtime.h>
#include <cuda_bf16.h>
#include <cuda_fp16.h>
#include <cfloat>
#include <math.h>
#include <cstdint>

// Problem constants
#define B_   8
#define N_   4096
#define M_   64
#define DIM_ 1024
#define H_   16
#define DH_  64
#define INNER_ 1024
#define KV2_  2048

// ==================== scratch (device globals) =============================
__device__ float    g_q[B_ * M_ * INNER_];
__device__ float    g_kv[(size_t)B_ * N_ * KV2_];
__device__ float    g_sim[(size_t)B_ * H_ * M_ * N_];
__device__ unsigned g_rmax_ord[B_ * H_ * M_];     // ordered-uint rowmax
__device__ float    g_attnout[B_ * M_ * INNER_];
__device__ float    g_losspart[B_ * H_];

// ==================== helpers =============================================
__device__ __forceinline__ uint32_t smem_u32(const void* p) {
    uint32_t a;
    asm("{ .reg .u64 t; cvta.to.shared.u64 t, %1; cvt.u32.u64 %0, t; }" : "=r"(a) : "l"(p));
    return a;
}
__device__ __forceinline__ uint32_t lds32(uint32_t a) {
    uint32_t v;
    asm volatile("ld.shared.b32 %0, [%1];" : "=r"(v) : "r"(a));
    return v;
}
#define LDMX4(r, addr) \
    asm volatile("ldmatrix.sync.aligned.m8n8.x4.shared.b16 {%0,%1,%2,%3}, [%4];" \
        : "=r"((r)[0]), "=r"((r)[1]), "=r"((r)[2]), "=r"((r)[3]) : "r"(addr))
#define MMA_F16(c, a, b) \
    asm volatile("mma.sync.aligned.m16n8k16.row.col.f32.f16.f16.f32 " \
        "{%0,%1,%2,%3}, {%4,%5,%6,%7}, {%8,%9}, {%0,%1,%2,%3};" \
        : "+f"((c)[0]), "+f"((c)[1]), "+f"((c)[2]), "+f"((c)[3]) \
        : "r"((a)[0]), "r"((a)[1]), "r"((a)[2]), "r"((a)[3]), "r"((b)[0]), "r"((b)[1]))

__device__ __forceinline__ uint2 hi_pack_h(float4 v) {
    __half2 p0(__float2half_rn(v.x), __float2half_rn(v.y));
    __half2 p1(__float2half_rn(v.z), __float2half_rn(v.w));
    uint2 r;
    r.x = *reinterpret_cast<uint32_t*>(&p0);
    r.y = *reinterpret_cast<uint32_t*>(&p1);
    return r;
}
__device__ __forceinline__ uint2 lo_pack_h(float4 v) {
    float4 l;
    l.x = v.x - __half2float(__float2half_rn(v.x));
    l.y = v.y - __half2float(__float2half_rn(v.y));
    l.z = v.z - __half2float(__float2half_rn(v.z));
    l.w = v.w - __half2float(__float2half_rn(v.w));
    return hi_pack_h(l);
}
// float <-> order-preserving uint
__device__ __forceinline__ unsigned f2o(float f) {
    unsigned b = __float_as_uint(f);
    return (b & 0x80000000u) ? ~b : (b | 0x80000000u);
}
__device__ __forceinline__ float o2f(unsigned u) {
    return __uint_as_float((u & 0x80000000u) ? (u ^ 0x80000000u) : ~u);
}

// ==================== fp16 2-pass GEMM via mma.sync ========================
// C[Mg x Ng] = alpha * A * B^T; A,B fp32 K-contiguous.
// acc = Ahi*Bh + Alo*Bh  (A exact via hi/lo fp16 split; only B rounding error)
// Tile 128x128, BK=32, 8 warps (2x4), warp tile 64x32, double-buffered smem.
#define TILE_BYTES   10240      // 128 rows * 80 B
#define STAGE_BYTES  30720      // 3 tiles (Ahi, Alo, Bh)
#define GSMEM_BYTES  61440      // 2 stages

__global__ __launch_bounds__(256, 1) void gemm_mma_kernel(
    const float* __restrict__ A, const float* __restrict__ Bm, float* __restrict__ C,
    int Ng, int Kg, float alpha)
{
    extern __shared__ char sm[];
    const uint32_t smb = smem_u32(sm);
    const int tid  = threadIdx.x;
    const int lane = tid & 31;
    const int wid  = tid >> 5;
    const int wm   = wid >> 2;
    const int wn   = wid & 3;
    const int row0 = blockIdx.y * 128;
    const int col0 = blockIdx.x * 128;

    float acc[4][4][4];
#pragma unroll
    for (int mt = 0; mt < 4; mt++)
#pragma unroll
        for (int nt = 0; nt < 4; nt++)
#pragma unroll
            for (int e = 0; e < 4; e++) acc[mt][nt][e] = 0.f;

    float4 ra[4], rb[4];
    const int rr = tid >> 3;
    const int cc = tid & 7;

#define LDG_TILES(k0) do { \
    _Pragma("unroll") \
    for (int i = 0; i < 4; i++) { \
        ra[i] = *reinterpret_cast<const float4*>(&A[(size_t)(row0 + rr + i * 32) * Kg + (k0) + cc * 4]); \
        rb[i] = *reinterpret_cast<const float4*>(&Bm[(size_t)(col0 + rr + i * 32) * Kg + (k0) + cc * 4]); \
    } } while (0)

#define STS_TILES(s) do { \
    char* sbp = sm + (s) * STAGE_BYTES; \
    _Pragma("unroll") \
    for (int i = 0; i < 4; i++) { \
        int off = (rr + i * 32) * 80 + cc * 8; \
        *reinterpret_cast<uint2*>(sbp + off)                  = hi_pack_h(ra[i]); \
        *reinterpret_cast<uint2*>(sbp + TILE_BYTES + off)     = lo_pack_h(ra[i]); \
        *reinterpret_cast<uint2*>(sbp + 2 * TILE_BYTES + off) = hi_pack_h(rb[i]); \
    } } while (0)

#define COMPUTE(s) do { \
    uint32_t sb = smb + (s) * STAGE_BYTES; \
    _Pragma("unroll") \
    for (int ks = 0; ks < 2; ks++) { \
        uint32_t ah[4][4], al[4][4], bh[4][2]; \
        _Pragma("unroll") \
        for (int mt = 0; mt < 4; mt++) { \
            uint32_t ad = sb + (uint32_t)(wm * 64 + mt * 16 + (lane & 15)) * 80 \
                          + ks * 32 + (lane >> 4) * 16; \
            LDMX4(ah[mt], ad); \
            LDMX4(al[mt], ad + TILE_BYTES); \
        } \
        _Pragma("unroll") \
        for (int nt = 0; nt < 4; nt++) { \
            uint32_t bd = sb + 2 * TILE_BYTES \
                          + (uint32_t)(wn * 32 + nt * 8 + (lane >> 2)) * 80 \
                          + (lane & 3) * 4 + ks * 32; \
            bh[nt][0] = lds32(bd); bh[nt][1] = lds32(bd + 16); \
        } \
        _Pragma("unroll") \
        for (int mt = 0; mt < 4; mt++) \
        _Pragma("unroll") \
        for (int nt = 0; nt < 4; nt++) { \
            MMA_F16(acc[mt][nt], ah[mt], bh[nt]); \
            MMA_F16(acc[mt][nt], al[mt], bh[nt]); \
        } \
    } } while (0)

    LDG_TILES(0);
    STS_TILES(0);
    __syncthreads();

    const int nk = Kg >> 5;
    for (int k = 0; k < nk; k++) {
        if (k + 1 < nk) LDG_TILES((k + 1) * 32);
        COMPUTE(k & 1);
        if (k + 1 < nk) STS_TILES((k + 1) & 1);
        __syncthreads();
    }

#pragma unroll
    for (int mt = 0; mt < 4; mt++) {
        int r = row0 + wm * 64 + mt * 16 + (lane >> 2);
#pragma unroll
        for (int nt = 0; nt < 4; nt++) {
            int c = col0 + wn * 32 + nt * 8 + (lane & 3) * 2;
            float2 v0 = make_float2(alpha * acc[mt][nt][0], alpha * acc[mt][nt][1]);
            float2 v1 = make_float2(alpha * acc[mt][nt][2], alpha * acc[mt][nt][3]);
            *reinterpret_cast<float2*>(&C[(size_t)r * Ng + c]) = v0;
            *reinterpret_cast<float2*>(&C[(size_t)(r + 8) * Ng + c]) = v1;
        }
    }
#undef LDG_TILES
#undef STS_TILES
#undef COMPUTE
}

// ==================== init kernels ========================================
__global__ void init_rmax_kernel() {
    int i = blockIdx.x * 256 + threadIdx.x;
    if (i < B_ * H_ * M_) g_rmax_ord[i] = 0u;   // below any real f2o value
}
__global__ void zloss_kernel() {
    if (threadIdx.x < B_ * H_) g_losspart[threadIdx.x] = 0.f;
}

// ==================== K3: sim + mask + fused rowmax =======================
__global__ __launch_bounds__(256) void sim_kernel(const int* __restrict__ mask)
{
    const int bh = blockIdx.y;
    const int b  = bh >> 4;
    const int h  = bh & 15;
    const int n0 = blockIdx.x * 64;
    const int tid = threadIdx.x;

    __shared__ float qs[64][65];
    __shared__ float ks[64][65];
    __shared__ float redm[64][17];

    for (int s = tid; s < 4096; s += 256) {
        int r = s >> 6, d = s & 63;
        qs[r][d] = g_q[(size_t)(b * M_ + r) * INNER_ + h * DH_ + d];
        ks[r][d] = g_kv[((size_t)b * N_ + n0 + r) * KV2_ + h * DH_ + d];
    }
    __syncthreads();

    const int ty = tid >> 4, tx = tid & 15;
    float acc[4][4];
#pragma unroll
    for (int u = 0; u < 4; u++)
#pragma unroll
        for (int v = 0; v < 4; v++) acc[u][v] = 0.f;

#pragma unroll 8
    for (int d = 0; d < 64; d++) {
        float a[4], c[4];
#pragma unroll
        for (int u = 0; u < 4; u++) a[u] = qs[ty + 16 * u][d];
#pragma unroll
        for (int v = 0; v < 4; v++) c[v] = ks[tx + 16 * v][d];
#pragma unroll
        for (int u = 0; u < 4; u++)
#pragma unroll
            for (int v = 0; v < 4; v++) acc[u][v] += a[u] * c[v];
    }

#pragma unroll
    for (int u = 0; u < 4; u++) {
        int i = ty + 16 * u;
        float rm = -FLT_MAX;
#pragma unroll
        for (int v = 0; v < 4; v++) {
            int n = n0 + tx + 16 * v;
            float val = (mask[b * N_ + n] != 0) ? -FLT_MAX : acc[u][v];
            g_sim[((size_t)bh * M_ + i) * N_ + n] = val;
            rm = fmaxf(rm, val);
        }
        redm[i][tx] = rm;
    }
    __syncthreads();
    if (tid < 64) {
        float m = redm[tid][0];
#pragma unroll
        for (int t = 1; t < 16; t++) m = fmaxf(m, redm[tid][t]);
        atomicMax(&g_rmax_ord[bh * M_ + tid], f2o(m));
    }
}

// ==================== K6: softmax + PV + fused column variance loss =======
__global__ __launch_bounds__(256) void pv_kernel(const int* __restrict__ mask)
{
    const int bh = blockIdx.x;
    const int b  = bh >> 4;
    const int h  = bh & 15;
    const int tid = threadIdx.x;

    __shared__ float ps[64][65];
    __shared__ float vs[64][65];
    __shared__ float denom[64];
    __shared__ float rs[64];
    __shared__ float colred[2][4][64];
    __shared__ float lred[64];

    if (tid < 64) { denom[tid] = 0.f; rs[tid] = o2f(g_rmax_ord[bh * M_ + tid]); }
    __syncthreads();

    const int cq = tid >> 6;      // 0..3 (row quarter)
    const int ccol = tid & 63;    // tile column
    const int ty = tid >> 4, tx = tid & 15;
    float acc[4][4];
#pragma unroll
    for (int u = 0; u < 4; u++)
#pragma unroll
        for (int c = 0; c < 4; c++) acc[u][c] = 0.f;
    float lossloc = 0.f;          // used by tid < 64

    for (int jt = 0; jt < 64; jt++) {
        const int j0 = jt * 64;
        float st = 0.f, st2 = 0.f;
#pragma unroll 4
        for (int k = 0; k < 16; k++) {
            int r = cq + 4 * k;
            float sv = g_sim[((size_t)bh * M_ + r) * N_ + j0 + ccol];
            float t = sv - rs[r];
            ps[r][ccol] = expf(t);
            st += t; st2 += t * t;
            vs[r][ccol] = g_kv[((size_t)b * N_ + j0 + r) * KV2_ + INNER_ + h * DH_ + ccol];
        }
        colred[0][cq][ccol] = st;
        colred[1][cq][ccol] = st2;
        __syncthreads();

        if (tid < 64) {
            // column variance loss for column j0+tid
            if (mask[b * N_ + j0 + tid] == 0) {
                float s  = colred[0][0][tid] + colred[0][1][tid] + colred[0][2][tid] + colred[0][3][tid];
                float ss = colred[1][0][tid] + colred[1][1][tid] + colred[1][2][tid] + colred[1][3][tid];
                float var = (ss - s * s * (1.0f / 64.f)) * (1.0f / 63.f);
                float sd  = sqrtf(var + 1e-4f);
                lossloc += fmaxf(1.0f - sd, 0.0f);
            }
            // softmax denominator for row tid
            float sde = 0.f;
#pragma unroll 8
            for (int j = 0; j < 64; j++) sde += ps[tid][j];
            denom[tid] += sde;
        }
#pragma unroll 4
        for (int j = 0; j < 64; j++) {
            float pv[4], vv[4];
#pragma unroll
            for (int u = 0; u < 4; u++) pv[u] = ps[ty + 16 * u][j];
#pragma unroll
            for (int c = 0; c < 4; c++) vv[c] = vs[j][tx + 16 * c];
#pragma unroll
            for (int u = 0; u < 4; u++)
#pragma unroll
                for (int c = 0; c < 4; c++) acc[u][c] += pv[u] * vv[c];
        }
        __syncthreads();
    }

#pragma unroll
    for (int u = 0; u < 4; u++) {
        int i = ty + 16 * u;
        float inv = 1.0f / denom[i];
#pragma unroll
        for (int c = 0; c < 4; c++) {
            int d = tx + 16 * c;
            g_attnout[((size_t)b * M_ + i) * INNER_ + h * DH_ + d] = acc[u][c] * inv;
        }
    }

    if (tid < 64) lred[tid] = lossloc;
    __syncthreads();
    if (tid < 32) lred[tid] += lred[tid + 32];
    __syncthreads();
    if (tid == 0) {
        float s = 0.f;
#pragma unroll
        for (int t = 0; t < 32; t++) s += lred[t];
        g_losspart[bh] = s;
    }
}

__global__ __launch_bounds__(128) void loss_final_kernel(float* __restrict__ out, int idx)
{
    __shared__ float red[128];
    red[threadIdx.x] = g_losspart[threadIdx.x];
    __syncthreads();
    for (int t = 64; t > 0; t >>= 1) {
        if (threadIdx.x < t) red[threadIdx.x] += red[threadIdx.x + t];
        __syncthreads();
    }
    if (threadIdx.x == 0) out[idx] = red[0] * (1.0f / (float)(B_ * H_ * N_));
}

// ==================== launch ==============================================
extern "C" void kernel_launch(void* const* d_in, const int* in_sizes, int n_in,
                              void* d_out, int out_size)
{
    const float* x       = (const float*)d_in[0];
    const float* latents = (const float*)d_in[1];
    const int*   mask    = (const int*)d_in[2];
    const float* Wq      = (const float*)d_in[3];
    const float* Wkv     = (const float*)d_in[4];
    const float* Wout    = (const float*)d_in[5];
    float*       out     = (float*)d_out;

    cudaFuncSetAttribute(gemm_mma_kernel, cudaFuncAttributeMaxDynamicSharedMemorySize, GSMEM_BYTES);

    void *pq, *pkv, *pattn;
    cudaGetSymbolAddress(&pq, g_q);
    cudaGetSymbolAddress(&pkv, g_kv);
    cudaGetSymbolAddress(&pattn, g_attnout);

    // L1: init rowmax
    init_rmax_kernel<<<(B_ * H_ * M_ + 255) / 256, 256>>>();

    // L2: q = latents @ Wq^T * scale   (512 x 1024, K=1024)
    gemm_mma_kernel<<<dim3(INNER_ / 128, (B_ * M_) / 128), 256, GSMEM_BYTES>>>(
        latents, Wq, (float*)pq, INNER_, DIM_, 0.125f);

    // L3: zero loss partials (also positions K2 at launch #4 for ncu)
    zloss_kernel<<<1, 128>>>();

    // L4: kv = x @ Wkv^T               (32768 x 2048, K=1024)
    gemm_mma_kernel<<<dim3(KV2_ / 128, (B_ * N_) / 128), 256, GSMEM_BYTES>>>(
        x, Wkv, (float*)pkv, KV2_, DIM_, 1.0f);

    // L5: sim + mask + rowmax
    sim_kernel<<<dim3(N_ / 64, B_ * H_), 256>>>(mask);

    // L6: softmax + PV + variance loss partials
    pv_kernel<<<B_ * H_, 256>>>(mask);

    // L7: loss finalize
    loss_final_kernel<<<1, 128>>>(out, out_size - 1);

    // L8: out = attn_out @ Wout^T      (512 x 1024, K=1024)
    gemm_mma_kernel<<<dim3(DIM_ / 128, (B_ * M_) / 128), 256, GSMEM_BYTES>>>(
        (const float*)pattn, Wout, out, DIM_, INNER_, 1.0f);
}

// round 6
// speedup vs baseline: 3.4036x; 1.1259x over previous
#include <cuda_runtime.h>
#include <cuda_fp16.h>
#include <cfloat>
#include <math.h>
#include <cstdint>

#define B_   8
#define N_   4096
#define M_   64
#define DIM_ 1024
#define H_   16
#define DH_  64
#define INNER_ 1024
#define KV2_  2048

// ==================== scratch =============================================
__device__ float    g_q[B_ * M_ * INNER_];
__device__ float    g_kv[(size_t)B_ * N_ * KV2_];
__device__ float    g_sim[(size_t)B_ * H_ * M_ * N_];
__device__ unsigned g_rmax_ord[B_ * H_ * M_];
__device__ float    g_attnout[B_ * M_ * INNER_];
__device__ float    g_losspart[B_ * H_];

// fp16 split buffers
__device__ __half g_xh[(size_t)B_ * N_ * DIM_];
__device__ __half g_xl[(size_t)B_ * N_ * DIM_];
__device__ __half g_wkvh[KV2_ * DIM_];
__device__ __half g_wqh[INNER_ * DIM_];
__device__ __half g_wouth[DIM_ * INNER_];
__device__ __half g_lath[B_ * M_ * DIM_];
__device__ __half g_latl[B_ * M_ * DIM_];
__device__ __half g_ah[B_ * M_ * INNER_];
__device__ __half g_al[B_ * M_ * INNER_];

// ==================== helpers =============================================
__device__ __forceinline__ uint32_t smem_u32(const void* p) {
    uint32_t a;
    asm("{ .reg .u64 t; cvta.to.shared.u64 t, %1; cvt.u32.u64 %0, t; }" : "=r"(a) : "l"(p));
    return a;
}
__device__ __forceinline__ uint32_t lds32(uint32_t a) {
    uint32_t v;
    asm volatile("ld.shared.b32 %0, [%1];" : "=r"(v) : "r"(a));
    return v;
}
#define LDMX4(r, addr) \
    asm volatile("ldmatrix.sync.aligned.m8n8.x4.shared.b16 {%0,%1,%2,%3}, [%4];" \
        : "=r"((r)[0]), "=r"((r)[1]), "=r"((r)[2]), "=r"((r)[3]) : "r"(addr))
#define MMA_F16(c, a, b) \
    asm volatile("mma.sync.aligned.m16n8k16.row.col.f32.f16.f16.f32 " \
        "{%0,%1,%2,%3}, {%4,%5,%6,%7}, {%8,%9}, {%0,%1,%2,%3};" \
        : "+f"((c)[0]), "+f"((c)[1]), "+f"((c)[2]), "+f"((c)[3]) \
        : "r"((a)[0]), "r"((a)[1]), "r"((a)[2]), "r"((a)[3]), "r"((b)[0]), "r"((b)[1]))
#define CP_ASYNC16(dst, src) \
    asm volatile("cp.async.cg.shared.global [%0], [%1], 16;" :: "r"(dst), "l"(src) : "memory")
#define CP_COMMIT asm volatile("cp.async.commit_group;" ::: "memory")
#define CP_WAIT1  asm volatile("cp.async.wait_group 1;" ::: "memory")
#define CP_WAIT0  asm volatile("cp.async.wait_group 0;" ::: "memory")
#define SW128(off) ((off) ^ (((off) >> 3) & 0x70))

__device__ __forceinline__ uint2 hi_pack_h(float4 v) {
    __half2 p0(__float2half_rn(v.x), __float2half_rn(v.y));
    __half2 p1(__float2half_rn(v.z), __float2half_rn(v.w));
    uint2 r;
    r.x = *reinterpret_cast<uint32_t*>(&p0);
    r.y = *reinterpret_cast<uint32_t*>(&p1);
    return r;
}
__device__ __forceinline__ uint2 lo_pack_h(float4 v) {
    float4 l;
    l.x = v.x - __half2float(__float2half_rn(v.x));
    l.y = v.y - __half2float(__float2half_rn(v.y));
    l.z = v.z - __half2float(__float2half_rn(v.z));
    l.w = v.w - __half2float(__float2half_rn(v.w));
    return hi_pack_h(l);
}
__device__ __forceinline__ unsigned f2o(float f) {
    unsigned b = __float_as_uint(f);
    return (b & 0x80000000u) ? ~b : (b | 0x80000000u);
}
__device__ __forceinline__ float o2f(unsigned u) {
    return __uint_as_float((u & 0x80000000u) ? (u ^ 0x80000000u) : ~u);
}

// ==================== split kernels =======================================
__global__ __launch_bounds__(256) void split2_kernel(
    const float* __restrict__ src, __half* __restrict__ h, __half* __restrict__ l, int n4)
{
    int i = blockIdx.x * 256 + threadIdx.x;
    if (i >= n4) return;
    float4 v = reinterpret_cast<const float4*>(src)[i];
    reinterpret_cast<uint2*>(h)[i] = hi_pack_h(v);
    reinterpret_cast<uint2*>(l)[i] = lo_pack_h(v);
}

// One kernel: split1 Wkv/Wq/Wout, split2 latents, init rmax, zero loss.
#define PR_WKV  524288            // 2048*1024/4
#define PR_WQ   (PR_WKV + 262144)
#define PR_WOUT (PR_WQ + 262144)
#define PR_LAT  (PR_WOUT + 131072)
#define PR_RM   (PR_LAT + 1024)
#define PR_END  (PR_RM + 128)
__global__ __launch_bounds__(256) void prep_kernel(
    const float* __restrict__ Wkv, const float* __restrict__ Wq,
    const float* __restrict__ Wout, const float* __restrict__ latents)
{
    int id = blockIdx.x * 256 + threadIdx.x;
    if (id < PR_WKV) {
        float4 v = reinterpret_cast<const float4*>(Wkv)[id];
        reinterpret_cast<uint2*>(g_wkvh)[id] = hi_pack_h(v);
    } else if (id < PR_WQ) {
        int i = id - PR_WKV;
        float4 v = reinterpret_cast<const float4*>(Wq)[i];
        reinterpret_cast<uint2*>(g_wqh)[i] = hi_pack_h(v);
    } else if (id < PR_WOUT) {
        int i = id - PR_WQ;
        float4 v = reinterpret_cast<const float4*>(Wout)[i];
        reinterpret_cast<uint2*>(g_wouth)[i] = hi_pack_h(v);
    } else if (id < PR_LAT) {
        int i = id - PR_WOUT;
        float4 v = reinterpret_cast<const float4*>(latents)[i];
        reinterpret_cast<uint2*>(g_lath)[i] = hi_pack_h(v);
        reinterpret_cast<uint2*>(g_latl)[i] = lo_pack_h(v);
    } else if (id < PR_RM) {
        g_rmax_ord[id - PR_LAT] = 0u;
    } else if (id < PR_END) {
        g_losspart[id - PR_RM] = 0.f;
    }
}

// ==================== fp16 GEMM, cp.async 3-stage pipeline ================
// C = alpha * (Ah + Al) * Bh^T; all operands fp16 K-contiguous, C fp32.
// Tile 128x128, BK=64, 8 warps (2x4), 3-stage cp.async ring, SW128 smem.
#define A_TILE     16384        // 128 rows * 64 fp16 * 2B
#define STAGE_B    49152        // Ah + Al + Bh tiles
#define GSMEM_B    147456       // 3 stages

__global__ __launch_bounds__(256, 1) void gemm16_kernel(
    const __half* __restrict__ Ah, const __half* __restrict__ Al,
    const __half* __restrict__ Bh, float* __restrict__ C,
    int Ng, int Kg, float alpha)
{
    extern __shared__ char sm[];
    const uint32_t smb = smem_u32(sm);
    const int tid  = threadIdx.x;
    const int lane = tid & 31;
    const int wid  = tid >> 5;
    const int wm   = wid >> 2;
    const int wn   = wid & 3;
    const int row0 = blockIdx.y * 128;
    const int col0 = blockIdx.x * 128;

    float acc[4][4][4];
#pragma unroll
    for (int mt = 0; mt < 4; mt++)
#pragma unroll
        for (int nt = 0; nt < 4; nt++)
#pragma unroll
            for (int e = 0; e < 4; e++) acc[mt][nt][e] = 0.f;

#define LOAD(i) do { \
    const int s_ = (i) % 3; \
    const uint32_t sb_ = smb + s_ * STAGE_B; \
    const int k0_ = (i) * 64; \
    _Pragma("unroll") \
    for (int c_ = 0; c_ < 4; c_++) { \
        int id_ = tid + c_ * 256; \
        int r_ = id_ >> 3, c16_ = id_ & 7; \
        uint32_t doff_ = SW128((uint32_t)(r_ * 128 + c16_ * 16)); \
        CP_ASYNC16(sb_ + doff_,              (const void*)&Ah[(size_t)(row0 + r_) * Kg + k0_ + c16_ * 8]); \
        CP_ASYNC16(sb_ + A_TILE + doff_,     (const void*)&Al[(size_t)(row0 + r_) * Kg + k0_ + c16_ * 8]); \
        CP_ASYNC16(sb_ + 2 * A_TILE + doff_, (const void*)&Bh[(size_t)(col0 + r_) * Kg + k0_ + c16_ * 8]); \
    } } while (0)

#define COMPUTE(s) do { \
    const uint32_t sb_ = smb + (s) * STAGE_B; \
    _Pragma("unroll") \
    for (int ks = 0; ks < 4; ks++) { \
        uint32_t ah[4][4], al[4][4], bh[4][2]; \
        _Pragma("unroll") \
        for (int mt = 0; mt < 4; mt++) { \
            uint32_t r_ = wm * 64 + mt * 16 + (lane & 15); \
            uint32_t off_ = SW128(r_ * 128 + ks * 32 + (lane >> 4) * 16); \
            LDMX4(ah[mt], sb_ + off_); \
            LDMX4(al[mt], sb_ + A_TILE + off_); \
        } \
        _Pragma("unroll") \
        for (int nt = 0; nt < 4; nt++) { \
            uint32_t n_ = wn * 32 + nt * 8 + (lane >> 2); \
            bh[nt][0] = lds32(sb_ + 2 * A_TILE + SW128(n_ * 128 + ks * 32 + (lane & 3) * 4)); \
            bh[nt][1] = lds32(sb_ + 2 * A_TILE + SW128(n_ * 128 + ks * 32 + 16 + (lane & 3) * 4)); \
        } \
        _Pragma("unroll") \
        for (int mt = 0; mt < 4; mt++) \
        _Pragma("unroll") \
        for (int nt = 0; nt < 4; nt++) { \
            MMA_F16(acc[mt][nt], ah[mt], bh[nt]); \
            MMA_F16(acc[mt][nt], al[mt], bh[nt]); \
        } \
    } } while (0)

    const int nk = Kg >> 6;
    LOAD(0); CP_COMMIT;
    LOAD(1); CP_COMMIT;
    for (int i = 0; i < nk; i++) {
        if (i + 1 < nk) { CP_WAIT1; } else { CP_WAIT0; }
        __syncthreads();
        if (i + 2 < nk) { LOAD(i + 2); CP_COMMIT; }
        COMPUTE(i % 3);
    }

#pragma unroll
    for (int mt = 0; mt < 4; mt++) {
        int r = row0 + wm * 64 + mt * 16 + (lane >> 2);
#pragma unroll
        for (int nt = 0; nt < 4; nt++) {
            int c = col0 + wn * 32 + nt * 8 + (lane & 3) * 2;
            float2 v0 = make_float2(alpha * acc[mt][nt][0], alpha * acc[mt][nt][1]);
            float2 v1 = make_float2(alpha * acc[mt][nt][2], alpha * acc[mt][nt][3]);
            *reinterpret_cast<float2*>(&C[(size_t)r * Ng + c]) = v0;
            *reinterpret_cast<float2*>(&C[(size_t)(r + 8) * Ng + c]) = v1;
        }
    }
#undef LOAD
#undef COMPUTE
}

// ==================== sim + mask + rowmax =================================
__global__ __launch_bounds__(256) void sim_kernel(const int* __restrict__ mask)
{
    const int bh = blockIdx.y;
    const int b  = bh >> 4;
    const int h  = bh & 15;
    const int n0 = blockIdx.x * 64;
    const int tid = threadIdx.x;

    __shared__ float qs[64][65];
    __shared__ float ks[64][65];
    __shared__ float redm[64][17];

    for (int s = tid; s < 4096; s += 256) {
        int r = s >> 6, d = s & 63;
        qs[r][d] = g_q[(size_t)(b * M_ + r) * INNER_ + h * DH_ + d];
        ks[r][d] = g_kv[((size_t)b * N_ + n0 + r) * KV2_ + h * DH_ + d];
    }
    __syncthreads();

    const int ty = tid >> 4, tx = tid & 15;
    float acc[4][4];
#pragma unroll
    for (int u = 0; u < 4; u++)
#pragma unroll
        for (int v = 0; v < 4; v++) acc[u][v] = 0.f;

#pragma unroll 8
    for (int d = 0; d < 64; d++) {
        float a[4], c[4];
#pragma unroll
        for (int u = 0; u < 4; u++) a[u] = qs[ty + 16 * u][d];
#pragma unroll
        for (int v = 0; v < 4; v++) c[v] = ks[tx + 16 * v][d];
#pragma unroll
        for (int u = 0; u < 4; u++)
#pragma unroll
            for (int v = 0; v < 4; v++) acc[u][v] += a[u] * c[v];
    }

#pragma unroll
    for (int u = 0; u < 4; u++) {
        int i = ty + 16 * u;
        float rm = -FLT_MAX;
#pragma unroll
        for (int v = 0; v < 4; v++) {
            int n = n0 + tx + 16 * v;
            float val = (mask[b * N_ + n] != 0) ? -FLT_MAX : acc[u][v];
            g_sim[((size_t)bh * M_ + i) * N_ + n] = val;
            rm = fmaxf(rm, val);
        }
        redm[i][tx] = rm;
    }
    __syncthreads();
    if (tid < 64) {
        float m = redm[tid][0];
#pragma unroll
        for (int t = 1; t < 16; t++) m = fmaxf(m, redm[tid][t]);
        atomicMax(&g_rmax_ord[bh * M_ + tid], f2o(m));
    }
}

// ==================== softmax + PV + variance loss ========================
__global__ __launch_bounds__(256) void pv_kernel(const int* __restrict__ mask)
{
    const int bh = blockIdx.x;
    const int b  = bh >> 4;
    const int h  = bh & 15;
    const int tid = threadIdx.x;

    __shared__ float ps[64][65];
    __shared__ float vs[64][65];
    __shared__ float denom[64];
    __shared__ float rs[64];
    __shared__ float colred[2][4][64];
    __shared__ float lred[64];

    if (tid < 64) { denom[tid] = 0.f; rs[tid] = o2f(g_rmax_ord[bh * M_ + tid]); }
    __syncthreads();

    const int cq = tid >> 6;
    const int ccol = tid & 63;
    const int ty = tid >> 4, tx = tid & 15;
    float acc[4][4];
#pragma unroll
    for (int u = 0; u < 4; u++)
#pragma unroll
        for (int c = 0; c < 4; c++) acc[u][c] = 0.f;
    float lossloc = 0.f;

    for (int jt = 0; jt < 64; jt++) {
        const int j0 = jt * 64;
        float st = 0.f, st2 = 0.f;
#pragma unroll 4
        for (int k = 0; k < 16; k++) {
            int r = cq + 4 * k;
            float sv = g_sim[((size_t)bh * M_ + r) * N_ + j0 + ccol];
            float t = sv - rs[r];
            ps[r][ccol] = expf(t);
            st += t; st2 += t * t;
            vs[r][ccol] = g_kv[((size_t)b * N_ + j0 + r) * KV2_ + INNER_ + h * DH_ + ccol];
        }
        colred[0][cq][ccol] = st;
        colred[1][cq][ccol] = st2;
        __syncthreads();

        if (tid < 64) {
            if (mask[b * N_ + j0 + tid] == 0) {
                float s  = colred[0][0][tid] + colred[0][1][tid] + colred[0][2][tid] + colred[0][3][tid];
                float ss = colred[1][0][tid] + colred[1][1][tid] + colred[1][2][tid] + colred[1][3][tid];
                float var = (ss - s * s * (1.0f / 64.f)) * (1.0f / 63.f);
                float sd  = sqrtf(var + 1e-4f);
                lossloc += fmaxf(1.0f - sd, 0.0f);
            }
            float sde = 0.f;
#pragma unroll 8
            for (int j = 0; j < 64; j++) sde += ps[tid][j];
            denom[tid] += sde;
        }
#pragma unroll 4
        for (int j = 0; j < 64; j++) {
            float pv[4], vv[4];
#pragma unroll
            for (int u = 0; u < 4; u++) pv[u] = ps[ty + 16 * u][j];
#pragma unroll
            for (int c = 0; c < 4; c++) vv[c] = vs[j][tx + 16 * c];
#pragma unroll
            for (int u = 0; u < 4; u++)
#pragma unroll
                for (int c = 0; c < 4; c++) acc[u][c] += pv[u] * vv[c];
        }
        __syncthreads();
    }

#pragma unroll
    for (int u = 0; u < 4; u++) {
        int i = ty + 16 * u;
        float inv = 1.0f / denom[i];
#pragma unroll
        for (int c = 0; c < 4; c++) {
            int d = tx + 16 * c;
            g_attnout[((size_t)b * M_ + i) * INNER_ + h * DH_ + d] = acc[u][c] * inv;
        }
    }

    if (tid < 64) lred[tid] = lossloc;
    __syncthreads();
    if (tid < 32) lred[tid] += lred[tid + 32];
    __syncthreads();
    if (tid == 0) {
        float s = 0.f;
#pragma unroll
        for (int t = 0; t < 32; t++) s += lred[t];
        g_losspart[bh] = s;
    }
}

__global__ __launch_bounds__(128) void loss_final_kernel(float* __restrict__ out, int idx)
{
    __shared__ float red[128];
    red[threadIdx.x] = g_losspart[threadIdx.x];
    __syncthreads();
    for (int t = 64; t > 0; t >>= 1) {
        if (threadIdx.x < t) red[threadIdx.x] += red[threadIdx.x + t];
        __syncthreads();
    }
    if (threadIdx.x == 0) out[idx] = red[0] * (1.0f / (float)(B_ * H_ * N_));
}

// ==================== launch ==============================================
extern "C" void kernel_launch(void* const* d_in, const int* in_sizes, int n_in,
                              void* d_out, int out_size)
{
    const float* x       = (const float*)d_in[0];
    const float* latents = (const float*)d_in[1];
    const int*   mask    = (const int*)d_in[2];
    const float* Wq      = (const float*)d_in[3];
    const float* Wkv     = (const float*)d_in[4];
    const float* Wout    = (const float*)d_in[5];
    float*       out     = (float*)d_out;

    cudaFuncSetAttribute(gemm16_kernel, cudaFuncAttributeMaxDynamicSharedMemorySize, GSMEM_B);

    void *pxh, *pxl, *pkvh, *pqh, *poh, *plh, *pll, *pah, *pal;
    void *pq, *pkv, *pattn;
    cudaGetSymbolAddress(&pxh, g_xh);   cudaGetSymbolAddress(&pxl, g_xl);
    cudaGetSymbolAddress(&pkvh, g_wkvh);
    cudaGetSymbolAddress(&pqh, g_wqh);  cudaGetSymbolAddress(&poh, g_wouth);
    cudaGetSymbolAddress(&plh, g_lath); cudaGetSymbolAddress(&pll, g_latl);
    cudaGetSymbolAddress(&pah, g_ah);   cudaGetSymbolAddress(&pal, g_al);
    cudaGetSymbolAddress(&pq, g_q);
    cudaGetSymbolAddress(&pkv, g_kv);
    cudaGetSymbolAddress(&pattn, g_attnout);

    // L1: split x -> fp16 hi/lo
    split2_kernel<<<(B_ * N_ * DIM_ / 4 + 255) / 256, 256>>>(
        x, (__half*)pxh, (__half*)pxl, B_ * N_ * DIM_ / 4);

    // L2: split weights + latents, init rmax/loss
    prep_kernel<<<(PR_END + 255) / 256, 256>>>(Wkv, Wq, Wout, latents);

    // L3: q = latents @ Wq^T * scale
    gemm16_kernel<<<dim3(INNER_ / 128, (B_ * M_) / 128), 256, GSMEM_B>>>(
        (const __half*)plh, (const __half*)pll, (const __half*)pqh,
        (float*)pq, INNER_, DIM_, 0.125f);

    // L4: kv = x @ Wkv^T   (profiled launch)
    gemm16_kernel<<<dim3(KV2_ / 128, (B_ * N_) / 128), 256, GSMEM_B>>>(
        (const __half*)pxh, (const __half*)pxl, (const __half*)pkvh,
        (float*)pkv, KV2_, DIM_, 1.0f);

    // L5: sim + mask + rowmax
    sim_kernel<<<dim3(N_ / 64, B_ * H_), 256>>>(mask);

    // L6: softmax + PV + variance loss
    pv_kernel<<<B_ * H_, 256>>>(mask);

    // L7: split attn output
    split2_kernel<<<(B_ * M_ * INNER_ / 4 + 255) / 256, 256>>>(
        (const float*)pattn, (__half*)pah, (__half*)pal, B_ * M_ * INNER_ / 4);

    // L8: loss finalize
    loss_final_kernel<<<1, 128>>>(out, out_size - 1);

    // L9: out = attn_out @ Wout^T
    gemm16_kernel<<<dim3(DIM_ / 128, (B_ * M_) / 128), 256, GSMEM_B>>>(
        (const __half*)pah, (const __half*)pal, (const __half*)poh,
        out, DIM_, INNER_, 1.0f);
}

// round 7
// speedup vs baseline: 3.8700x; 1.1371x over previous
#include <cuda_runtime.h>
#include <cuda_fp16.h>
#include <cfloat>
#include <math.h>
#include <cstdint>

#define B_   8
#define N_   4096
#define M_   64
#define DIM_ 1024
#define H_   16
#define DH_  64
#define INNER_ 1024
#define KV2_  2048
#define NCH_  4          // pv j-chunks

// ==================== scratch =============================================
__device__ float    g_q[B_ * M_ * INNER_];
__device__ float    g_kv[(size_t)B_ * N_ * KV2_];
__device__ float    g_sim[(size_t)B_ * H_ * M_ * N_];
__device__ unsigned g_rmax_ord[B_ * H_ * M_];
__device__ float    g_attnout[B_ * M_ * INNER_];
__device__ float    g_losspart[B_ * H_];
__device__ float    g_pvpart[B_ * H_ * NCH_ * M_ * DH_];   // 8 MB
__device__ float    g_denpart[B_ * H_ * NCH_ * M_];
__device__ float    g_losschunk[B_ * H_ * NCH_];

// fp16 split buffers
__device__ __half g_xh[(size_t)B_ * N_ * DIM_];
__device__ __half g_xl[(size_t)B_ * N_ * DIM_];
__device__ __half g_wkvh[KV2_ * DIM_];
__device__ __half g_wqh[INNER_ * DIM_];
__device__ __half g_wouth[DIM_ * INNER_];
__device__ __half g_lath[B_ * M_ * DIM_];
__device__ __half g_latl[B_ * M_ * DIM_];
__device__ __half g_ah[B_ * M_ * INNER_];
__device__ __half g_al[B_ * M_ * INNER_];

// ==================== helpers =============================================
__device__ __forceinline__ uint32_t smem_u32(const void* p) {
    uint32_t a;
    asm("{ .reg .u64 t; cvta.to.shared.u64 t, %1; cvt.u32.u64 %0, t; }" : "=r"(a) : "l"(p));
    return a;
}
__device__ __forceinline__ uint32_t lds32(uint32_t a) {
    uint32_t v;
    asm volatile("ld.shared.b32 %0, [%1];" : "=r"(v) : "r"(a));
    return v;
}
#define LDMX4(r, addr) \
    asm volatile("ldmatrix.sync.aligned.m8n8.x4.shared.b16 {%0,%1,%2,%3}, [%4];" \
        : "=r"((r)[0]), "=r"((r)[1]), "=r"((r)[2]), "=r"((r)[3]) : "r"(addr))
#define MMA_F16(c, a, b) \
    asm volatile("mma.sync.aligned.m16n8k16.row.col.f32.f16.f16.f32 " \
        "{%0,%1,%2,%3}, {%4,%5,%6,%7}, {%8,%9}, {%0,%1,%2,%3};" \
        : "+f"((c)[0]), "+f"((c)[1]), "+f"((c)[2]), "+f"((c)[3]) \
        : "r"((a)[0]), "r"((a)[1]), "r"((a)[2]), "r"((a)[3]), "r"((b)[0]), "r"((b)[1]))
#define CP_ASYNC16(dst, src) \
    asm volatile("cp.async.cg.shared.global [%0], [%1], 16;" :: "r"(dst), "l"(src) : "memory")
#define CP_COMMIT asm volatile("cp.async.commit_group;" ::: "memory")
#define CP_WAIT1  asm volatile("cp.async.wait_group 1;" ::: "memory")
#define CP_WAIT0  asm volatile("cp.async.wait_group 0;" ::: "memory")
#define SW128(off) ((off) ^ (((off) >> 3) & 0x70))

__device__ __forceinline__ uint2 hi_pack_h(float4 v) {
    __half2 p0(__float2half_rn(v.x), __float2half_rn(v.y));
    __half2 p1(__float2half_rn(v.z), __float2half_rn(v.w));
    uint2 r;
    r.x = *reinterpret_cast<uint32_t*>(&p0);
    r.y = *reinterpret_cast<uint32_t*>(&p1);
    return r;
}
__device__ __forceinline__ uint2 lo_pack_h(float4 v) {
    float4 l;
    l.x = v.x - __half2float(__float2half_rn(v.x));
    l.y = v.y - __half2float(__float2half_rn(v.y));
    l.z = v.z - __half2float(__float2half_rn(v.z));
    l.w = v.w - __half2float(__float2half_rn(v.w));
    return hi_pack_h(l);
}
__device__ __forceinline__ unsigned f2o(float f) {
    unsigned b = __float_as_uint(f);
    return (b & 0x80000000u) ? ~b : (b | 0x80000000u);
}
__device__ __forceinline__ float o2f(unsigned u) {
    return __uint_as_float((u & 0x80000000u) ? (u ^ 0x80000000u) : ~u);
}

// ==================== split kernels =======================================
__global__ __launch_bounds__(256) void split2_kernel(
    const float* __restrict__ src, __half* __restrict__ h, __half* __restrict__ l, int n4)
{
    int i = blockIdx.x * 256 + threadIdx.x;
    if (i >= n4) return;
    float4 v = reinterpret_cast<const float4*>(src)[i];
    reinterpret_cast<uint2*>(h)[i] = hi_pack_h(v);
    reinterpret_cast<uint2*>(l)[i] = lo_pack_h(v);
}

#define PR_WKV  524288
#define PR_WQ   (PR_WKV + 262144)
#define PR_WOUT (PR_WQ + 262144)
#define PR_LAT  (PR_WOUT + 131072)
#define PR_RM   (PR_LAT + 1024)
#define PR_END  (PR_RM + 128)
__global__ __launch_bounds__(256) void prep_kernel(
    const float* __restrict__ Wkv, const float* __restrict__ Wq,
    const float* __restrict__ Wout, const float* __restrict__ latents)
{
    int id = blockIdx.x * 256 + threadIdx.x;
    if (id < PR_WKV) {
        float4 v = reinterpret_cast<const float4*>(Wkv)[id];
        reinterpret_cast<uint2*>(g_wkvh)[id] = hi_pack_h(v);
    } else if (id < PR_WQ) {
        int i = id - PR_WKV;
        float4 v = reinterpret_cast<const float4*>(Wq)[i];
        reinterpret_cast<uint2*>(g_wqh)[i] = hi_pack_h(v);
    } else if (id < PR_WOUT) {
        int i = id - PR_WQ;
        float4 v = reinterpret_cast<const float4*>(Wout)[i];
        reinterpret_cast<uint2*>(g_wouth)[i] = hi_pack_h(v);
    } else if (id < PR_LAT) {
        int i = id - PR_WOUT;
        float4 v = reinterpret_cast<const float4*>(latents)[i];
        reinterpret_cast<uint2*>(g_lath)[i] = hi_pack_h(v);
        reinterpret_cast<uint2*>(g_latl)[i] = lo_pack_h(v);
    } else if (id < PR_RM) {
        g_rmax_ord[id - PR_LAT] = 0u;
    } else if (id < PR_END) {
        g_losspart[id - PR_RM] = 0.f;
    }
}

// ==================== fp16 GEMM, cp.async 3-stage pipeline ================
#define A_TILE     16384
#define STAGE_B    49152
#define GSMEM_B    147456

__global__ __launch_bounds__(256, 1) void gemm16_kernel(
    const __half* __restrict__ Ah, const __half* __restrict__ Al,
    const __half* __restrict__ Bh, float* __restrict__ C,
    int Ng, int Kg, float alpha)
{
    extern __shared__ char sm[];
    const uint32_t smb = smem_u32(sm);
    const int tid  = threadIdx.x;
    const int lane = tid & 31;
    const int wid  = tid >> 5;
    const int wm   = wid >> 2;
    const int wn   = wid & 3;
    const int row0 = blockIdx.y * 128;
    const int col0 = blockIdx.x * 128;

    float acc[4][4][4];
#pragma unroll
    for (int mt = 0; mt < 4; mt++)
#pragma unroll
        for (int nt = 0; nt < 4; nt++)
#pragma unroll
            for (int e = 0; e < 4; e++) acc[mt][nt][e] = 0.f;

#define LOAD(i) do { \
    const int s_ = (i) % 3; \
    const uint32_t sb_ = smb + s_ * STAGE_B; \
    const int k0_ = (i) * 64; \
    _Pragma("unroll") \
    for (int c_ = 0; c_ < 4; c_++) { \
        int id_ = tid + c_ * 256; \
        int r_ = id_ >> 3, c16_ = id_ & 7; \
        uint32_t doff_ = SW128((uint32_t)(r_ * 128 + c16_ * 16)); \
        CP_ASYNC16(sb_ + doff_,              (const void*)&Ah[(size_t)(row0 + r_) * Kg + k0_ + c16_ * 8]); \
        CP_ASYNC16(sb_ + A_TILE + doff_,     (const void*)&Al[(size_t)(row0 + r_) * Kg + k0_ + c16_ * 8]); \
        CP_ASYNC16(sb_ + 2 * A_TILE + doff_, (const void*)&Bh[(size_t)(col0 + r_) * Kg + k0_ + c16_ * 8]); \
    } } while (0)

#define COMPUTE(s) do { \
    const uint32_t sb_ = smb + (s) * STAGE_B; \
    _Pragma("unroll") \
    for (int ks = 0; ks < 4; ks++) { \
        uint32_t ah[4][4], al[4][4], bh[4][2]; \
        _Pragma("unroll") \
        for (int mt = 0; mt < 4; mt++) { \
            uint32_t r_ = wm * 64 + mt * 16 + (lane & 15); \
            uint32_t off_ = SW128(r_ * 128 + ks * 32 + (lane >> 4) * 16); \
            LDMX4(ah[mt], sb_ + off_); \
            LDMX4(al[mt], sb_ + A_TILE + off_); \
        } \
        _Pragma("unroll") \
        for (int nt = 0; nt < 4; nt++) { \
            uint32_t n_ = wn * 32 + nt * 8 + (lane >> 2); \
            bh[nt][0] = lds32(sb_ + 2 * A_TILE + SW128(n_ * 128 + ks * 32 + (lane & 3) * 4)); \
            bh[nt][1] = lds32(sb_ + 2 * A_TILE + SW128(n_ * 128 + ks * 32 + 16 + (lane & 3) * 4)); \
        } \
        _Pragma("unroll") \
        for (int mt = 0; mt < 4; mt++) \
        _Pragma("unroll") \
        for (int nt = 0; nt < 4; nt++) { \
            MMA_F16(acc[mt][nt], ah[mt], bh[nt]); \
            MMA_F16(acc[mt][nt], al[mt], bh[nt]); \
        } \
    } } while (0)

    const int nk = Kg >> 6;
    LOAD(0); CP_COMMIT;
    LOAD(1); CP_COMMIT;
    for (int i = 0; i < nk; i++) {
        if (i + 1 < nk) { CP_WAIT1; } else { CP_WAIT0; }
        __syncthreads();
        if (i + 2 < nk) { LOAD(i + 2); CP_COMMIT; }
        COMPUTE(i % 3);
    }

#pragma unroll
    for (int mt = 0; mt < 4; mt++) {
        int r = row0 + wm * 64 + mt * 16 + (lane >> 2);
#pragma unroll
        for (int nt = 0; nt < 4; nt++) {
            int c = col0 + wn * 32 + nt * 8 + (lane & 3) * 2;
            float2 v0 = make_float2(alpha * acc[mt][nt][0], alpha * acc[mt][nt][1]);
            float2 v1 = make_float2(alpha * acc[mt][nt][2], alpha * acc[mt][nt][3]);
            *reinterpret_cast<float2*>(&C[(size_t)r * Ng + c]) = v0;
            *reinterpret_cast<float2*>(&C[(size_t)(r + 8) * Ng + c]) = v1;
        }
    }
#undef LOAD
#undef COMPUTE
}

// ==================== sim + mask + rowmax (8x8 blocking) ==================
// Block: 64 (M) x 128 (N), 128 threads, 8x8 per-thread tile. FMA-bound.
__global__ __launch_bounds__(128) void sim_kernel(const int* __restrict__ mask)
{
    const int bh = blockIdx.y;
    const int b  = bh >> 4;
    const int h  = bh & 15;
    const int n0 = blockIdx.x * 128;
    const int tid = threadIdx.x;
    const int ty = tid >> 4;     // 0..7  -> rows ty*8..+7
    const int tx = tid & 15;     // 0..15 -> cols tx*8..+7

    __shared__ float qs[64][65];
    __shared__ float ks[128][65];
    __shared__ float redm[64][17];

    // fill qs: 1024 float4 chunks
    for (int s = tid; s < 1024; s += 128) {
        int r = s >> 4, c4 = s & 15;
        float4 v = *reinterpret_cast<const float4*>(
            &g_q[(size_t)(b * M_ + r) * INNER_ + h * DH_ + c4 * 4]);
        qs[r][c4 * 4 + 0] = v.x; qs[r][c4 * 4 + 1] = v.y;
        qs[r][c4 * 4 + 2] = v.z; qs[r][c4 * 4 + 3] = v.w;
    }
    // fill ks: 2048 float4 chunks
    for (int s = tid; s < 2048; s += 128) {
        int r = s >> 4, c4 = s & 15;
        float4 v = *reinterpret_cast<const float4*>(
            &g_kv[((size_t)b * N_ + n0 + r) * KV2_ + h * DH_ + c4 * 4]);
        ks[r][c4 * 4 + 0] = v.x; ks[r][c4 * 4 + 1] = v.y;
        ks[r][c4 * 4 + 2] = v.z; ks[r][c4 * 4 + 3] = v.w;
    }
    __syncthreads();

    float acc[8][8];
#pragma unroll
    for (int u = 0; u < 8; u++)
#pragma unroll
        for (int v = 0; v < 8; v++) acc[u][v] = 0.f;

#pragma unroll 4
    for (int d = 0; d < 64; d++) {
        float a[8], c[8];
#pragma unroll
        for (int u = 0; u < 8; u++) a[u] = qs[ty * 8 + u][d];
#pragma unroll
        for (int v = 0; v < 8; v++) c[v] = ks[tx * 8 + v][d];
#pragma unroll
        for (int u = 0; u < 8; u++)
#pragma unroll
            for (int v = 0; v < 8; v++) acc[u][v] += a[u] * c[v];
    }

    // mask per column (8 cols per thread)
    int mk[8];
#pragma unroll
    for (int v = 0; v < 8; v++) mk[v] = mask[b * N_ + n0 + tx * 8 + v];

#pragma unroll
    for (int u = 0; u < 8; u++) {
        int i = ty * 8 + u;
        float rm = -FLT_MAX;
        float row[8];
#pragma unroll
        for (int v = 0; v < 8; v++) {
            float val = (mk[v] != 0) ? -FLT_MAX : acc[u][v];
            row[v] = val;
            rm = fmaxf(rm, val);
        }
        // vectorized store: 8 consecutive floats
        float4* dst = reinterpret_cast<float4*>(
            &g_sim[((size_t)bh * M_ + i) * N_ + n0 + tx * 8]);
        dst[0] = make_float4(row[0], row[1], row[2], row[3]);
        dst[1] = make_float4(row[4], row[5], row[6], row[7]);
        redm[i][tx] = rm;
    }
    __syncthreads();
    if (tid < 64) {
        float m = redm[tid][0];
#pragma unroll
        for (int t = 1; t < 16; t++) m = fmaxf(m, redm[tid][t]);
        atomicMax(&g_rmax_ord[bh * M_ + tid], f2o(m));
    }
}

// ==================== pv chunk: softmax num + PV partial + loss ===========
// grid (NCH_, 128); each block: 16 j-tiles of 64. Deterministic partials.
__global__ __launch_bounds__(256) void pv_chunk_kernel(const int* __restrict__ mask)
{
    const int ch = blockIdx.x;
    const int bh = blockIdx.y;
    const int b  = bh >> 4;
    const int h  = bh & 15;
    const int tid = threadIdx.x;

    __shared__ float ps[64][65];
    __shared__ float vs[64][65];
    __shared__ float rs[64];
    __shared__ float colred[2][4][64];
    __shared__ float lred[64];

    if (tid < 64) rs[tid] = o2f(g_rmax_ord[bh * M_ + tid]);
    __syncthreads();

    const int cq = tid >> 6;
    const int ccol = tid & 63;
    const int ty = tid >> 4, tx = tid & 15;
    float acc[4][4];
#pragma unroll
    for (int u = 0; u < 4; u++)
#pragma unroll
        for (int c = 0; c < 4; c++) acc[u][c] = 0.f;
    float lossloc = 0.f;
    float denloc = 0.f;     // rows owned by tid<64

    const int jt0 = ch * (64 / NCH_);
    for (int jt = jt0; jt < jt0 + 64 / NCH_; jt++) {
        const int j0 = jt * 64;
        float st = 0.f, st2 = 0.f;
#pragma unroll 4
        for (int k = 0; k < 16; k++) {
            int r = cq + 4 * k;
            float sv = g_sim[((size_t)bh * M_ + r) * N_ + j0 + ccol];
            float t = sv - rs[r];
            ps[r][ccol] = expf(t);
            st += t; st2 += t * t;
            vs[r][ccol] = g_kv[((size_t)b * N_ + j0 + r) * KV2_ + INNER_ + h * DH_ + ccol];
        }
        colred[0][cq][ccol] = st;
        colred[1][cq][ccol] = st2;
        __syncthreads();

        if (tid < 64) {
            if (mask[b * N_ + j0 + tid] == 0) {
                float s  = colred[0][0][tid] + colred[0][1][tid] + colred[0][2][tid] + colred[0][3][tid];
                float ss = colred[1][0][tid] + colred[1][1][tid] + colred[1][2][tid] + colred[1][3][tid];
                float var = (ss - s * s * (1.0f / 64.f)) * (1.0f / 63.f);
                float sd  = sqrtf(var + 1e-4f);
                lossloc += fmaxf(1.0f - sd, 0.0f);
            }
            float sde = 0.f;
#pragma unroll 8
            for (int j = 0; j < 64; j++) sde += ps[tid][j];
            denloc += sde;
        }
#pragma unroll 4
        for (int j = 0; j < 64; j++) {
            float pv[4], vv[4];
#pragma unroll
            for (int u = 0; u < 4; u++) pv[u] = ps[ty + 16 * u][j];
#pragma unroll
            for (int c = 0; c < 4; c++) vv[c] = vs[j][tx + 16 * c];
#pragma unroll
            for (int u = 0; u < 4; u++)
#pragma unroll
                for (int c = 0; c < 4; c++) acc[u][c] += pv[u] * vv[c];
        }
        __syncthreads();
    }

    // write partials
    float* pvb = &g_pvpart[((size_t)bh * NCH_ + ch) * M_ * DH_];
#pragma unroll
    for (int u = 0; u < 4; u++) {
        int i = ty + 16 * u;
#pragma unroll
        for (int c = 0; c < 4; c++) pvb[i * DH_ + tx + 16 * c] = acc[u][c];
    }
    if (tid < 64) g_denpart[(bh * NCH_ + ch) * M_ + tid] = denloc;

    if (tid < 64) lred[tid] = lossloc;
    __syncthreads();
    if (tid < 32) lred[tid] += lred[tid + 32];
    __syncthreads();
    if (tid == 0) {
        float s = 0.f;
#pragma unroll
        for (int t = 0; t < 32; t++) s += lred[t];
        g_losschunk[bh * NCH_ + ch] = s;
    }
}

// ==================== pv combine ==========================================
__global__ __launch_bounds__(256) void pv_combine_kernel()
{
    const int bh = blockIdx.x;
    const int b  = bh >> 4;
    const int h  = bh & 15;
    const int tid = threadIdx.x;

    __shared__ float dinv[64];
    if (tid < 64) {
        float d = 0.f;
#pragma unroll
        for (int c = 0; c < NCH_; c++) d += g_denpart[(bh * NCH_ + c) * M_ + tid];
        dinv[tid] = 1.0f / d;
    }
    if (tid == 64) {
        float s = 0.f;
#pragma unroll
        for (int c = 0; c < NCH_; c++) s += g_losschunk[bh * NCH_ + c];
        g_losspart[bh] = s;
    }
    __syncthreads();

    const float* pvb = &g_pvpart[(size_t)bh * NCH_ * M_ * DH_];
    for (int idx = tid; idx < M_ * DH_; idx += 256) {
        int i = idx >> 6, d = idx & 63;
        float s = 0.f;
#pragma unroll
        for (int c = 0; c < NCH_; c++) s += pvb[c * M_ * DH_ + idx];
        g_attnout[((size_t)b * M_ + i) * INNER_ + h * DH_ + d] = s * dinv[i];
    }
}

__global__ __launch_bounds__(128) void loss_final_kernel(float* __restrict__ out, int idx)
{
    __shared__ float red[128];
    red[threadIdx.x] = g_losspart[threadIdx.x];
    __syncthreads();
    for (int t = 64; t > 0; t >>= 1) {
        if (threadIdx.x < t) red[threadIdx.x] += red[threadIdx.x + t];
        __syncthreads();
    }
    if (threadIdx.x == 0) out[idx] = red[0] * (1.0f / (float)(B_ * H_ * N_));
}

// ==================== launch ==============================================
extern "C" void kernel_launch(void* const* d_in, const int* in_sizes, int n_in,
                              void* d_out, int out_size)
{
    const float* x       = (const float*)d_in[0];
    const float* latents = (const float*)d_in[1];
    const int*   mask    = (const int*)d_in[2];
    const float* Wq      = (const float*)d_in[3];
    const float* Wkv     = (const float*)d_in[4];
    const float* Wout    = (const float*)d_in[5];
    float*       out     = (float*)d_out;

    cudaFuncSetAttribute(gemm16_kernel, cudaFuncAttributeMaxDynamicSharedMemorySize, GSMEM_B);

    void *pxh, *pxl, *pkvh, *pqh, *poh, *plh, *pll, *pah, *pal;
    void *pq, *pattn;
    cudaGetSymbolAddress(&pxh, g_xh);   cudaGetSymbolAddress(&pxl, g_xl);
    cudaGetSymbolAddress(&pkvh, g_wkvh);
    cudaGetSymbolAddress(&pqh, g_wqh);  cudaGetSymbolAddress(&poh, g_wouth);
    cudaGetSymbolAddress(&plh, g_lath); cudaGetSymbolAddress(&pll, g_latl);
    cudaGetSymbolAddress(&pah, g_ah);   cudaGetSymbolAddress(&pal, g_al);
    cudaGetSymbolAddress(&pq, g_q);
    void* pkv; cudaGetSymbolAddress(&pkv, g_kv);
    cudaGetSymbolAddress(&pattn, g_attnout);

    // L1: split x -> fp16 hi/lo
    split2_kernel<<<(B_ * N_ * DIM_ / 4 + 255) / 256, 256>>>(
        x, (__half*)pxh, (__half*)pxl, B_ * N_ * DIM_ / 4);

    // L2: split weights + latents, init rmax/loss
    prep_kernel<<<(PR_END + 255) / 256, 256>>>(Wkv, Wq, Wout, latents);

    // L3: q = latents @ Wq^T * scale
    gemm16_kernel<<<dim3(INNER_ / 128, (B_ * M_) / 128), 256, GSMEM_B>>>(
        (const __half*)plh, (const __half*)pll, (const __half*)pqh,
        (float*)pq, INNER_, DIM_, 0.125f);

    // L4: kv = x @ Wkv^T   (profiled launch)
    gemm16_kernel<<<dim3(KV2_ / 128, (B_ * N_) / 128), 256, GSMEM_B>>>(
        (const __half*)pxh, (const __half*)pxl, (const __half*)pkvh,
        (float*)pkv, KV2_, DIM_, 1.0f);

    // L5: sim + mask + rowmax
    sim_kernel<<<dim3(N_ / 128, B_ * H_), 128>>>(mask);

    // L6: pv chunks (softmax + PV partials + variance loss)
    pv_chunk_kernel<<<dim3(NCH_, B_ * H_), 256>>>(mask);

    // L7: combine partials -> attnout + loss partials
    pv_combine_kernel<<<B_ * H_, 256>>>();

    // L8: split attn output
    split2_kernel<<<(B_ * M_ * INNER_ / 4 + 255) / 256, 256>>>(
        (const float*)pattn, (__half*)pah, (__half*)pal, B_ * M_ * INNER_ / 4);

    // L9: loss finalize
    loss_final_kernel<<<1, 128>>>(out, out_size - 1);

    // L10: out = attn_out @ Wout^T
    gemm16_kernel<<<dim3(DIM_ / 128, (B_ * M_) / 128), 256, GSMEM_B>>>(
        (const __half*)pah, (const __half*)pal, (const __half*)poh,
        out, DIM_, INNER_, 1.0f);
}

// round 8
// speedup vs baseline: 3.9026x; 1.0084x over previous
#include <cuda_runtime.h>
#include <cuda_fp16.h>
#include <cfloat>
#include <math.h>
#include <cstdint>

#define B_   8
#define N_   4096
#define M_   64
#define DIM_ 1024
#define H_   16
#define DH_  64
#define INNER_ 1024
#define KV2_  2048
#define NCH_  4

// ==================== scratch =============================================
__device__ float    g_q[B_ * M_ * INNER_];
__device__ float    g_kv[(size_t)B_ * N_ * KV2_];
__device__ float    g_sim[(size_t)B_ * H_ * M_ * N_];
__device__ unsigned g_rmax_ord[B_ * H_ * M_];
__device__ float    g_attnout[B_ * M_ * INNER_];
__device__ float    g_losspart[B_ * H_];
__device__ float    g_pvpart[B_ * H_ * NCH_ * M_ * DH_];
__device__ float    g_denpart[B_ * H_ * NCH_ * M_];
__device__ float    g_losschunk[B_ * H_ * NCH_];

// fp16 split buffers
__device__ __half g_xh[(size_t)B_ * N_ * DIM_];
__device__ __half g_xl[(size_t)B_ * N_ * DIM_];
__device__ __half g_wkvh[KV2_ * DIM_];
__device__ __half g_wqh[INNER_ * DIM_];
__device__ __half g_wouth[DIM_ * INNER_];
__device__ __half g_lath[B_ * M_ * DIM_];
__device__ __half g_latl[B_ * M_ * DIM_];
__device__ __half g_ah[B_ * M_ * INNER_];
__device__ __half g_al[B_ * M_ * INNER_];

// ==================== helpers =============================================
__device__ __forceinline__ uint32_t smem_u32(const void* p) {
    uint32_t a;
    asm("{ .reg .u64 t; cvta.to.shared.u64 t, %1; cvt.u32.u64 %0, t; }" : "=r"(a) : "l"(p));
    return a;
}
__device__ __forceinline__ uint32_t lds32(uint32_t a) {
    uint32_t v;
    asm volatile("ld.shared.b32 %0, [%1];" : "=r"(v) : "r"(a));
    return v;
}
#define LDMX4(r, addr) \
    asm volatile("ldmatrix.sync.aligned.m8n8.x4.shared.b16 {%0,%1,%2,%3}, [%4];" \
        : "=r"((r)[0]), "=r"((r)[1]), "=r"((r)[2]), "=r"((r)[3]) : "r"(addr))
#define MMA_F16(c, a, b) \
    asm volatile("mma.sync.aligned.m16n8k16.row.col.f32.f16.f16.f32 " \
        "{%0,%1,%2,%3}, {%4,%5,%6,%7}, {%8,%9}, {%0,%1,%2,%3};" \
        : "+f"((c)[0]), "+f"((c)[1]), "+f"((c)[2]), "+f"((c)[3]) \
        : "r"((a)[0]), "r"((a)[1]), "r"((a)[2]), "r"((a)[3]), "r"((b)[0]), "r"((b)[1]))
#define CP_ASYNC16(dst, src) \
    asm volatile("cp.async.cg.shared.global [%0], [%1], 16;" :: "r"(dst), "l"(src) : "memory")
#define CP_COMMIT asm volatile("cp.async.commit_group;" ::: "memory")
#define CP_WAIT1  asm volatile("cp.async.wait_group 1;" ::: "memory")
#define CP_WAIT0  asm volatile("cp.async.wait_group 0;" ::: "memory")
#define SW128(off) ((off) ^ (((off) >> 3) & 0x70))

__device__ __forceinline__ uint2 hi_pack_h(float4 v) {
    __half2 p0(__float2half_rn(v.x), __float2half_rn(v.y));
    __half2 p1(__float2half_rn(v.z), __float2half_rn(v.w));
    uint2 r;
    r.x = *reinterpret_cast<uint32_t*>(&p0);
    r.y = *reinterpret_cast<uint32_t*>(&p1);
    return r;
}
__device__ __forceinline__ uint2 lo_pack_h(float4 v) {
    float4 l;
    l.x = v.x - __half2float(__float2half_rn(v.x));
    l.y = v.y - __half2float(__float2half_rn(v.y));
    l.z = v.z - __half2float(__float2half_rn(v.z));
    l.w = v.w - __half2float(__float2half_rn(v.w));
    return hi_pack_h(l);
}
__device__ __forceinline__ unsigned f2o(float f) {
    unsigned b = __float_as_uint(f);
    return (b & 0x80000000u) ? ~b : (b | 0x80000000u);
}
__device__ __forceinline__ float o2f(unsigned u) {
    return __uint_as_float((u & 0x80000000u) ? (u ^ 0x80000000u) : ~u);
}

// ==================== split kernels =======================================
__global__ __launch_bounds__(256) void split2_kernel(
    const float* __restrict__ src, __half* __restrict__ h, __half* __restrict__ l, int n4)
{
    int i = blockIdx.x * 256 + threadIdx.x;
    if (i >= n4) return;
    float4 v = reinterpret_cast<const float4*>(src)[i];
    reinterpret_cast<uint2*>(h)[i] = hi_pack_h(v);
    reinterpret_cast<uint2*>(l)[i] = lo_pack_h(v);
}

#define PR_WKV  524288
#define PR_WQ   (PR_WKV + 262144)
#define PR_WOUT (PR_WQ + 262144)
#define PR_LAT  (PR_WOUT + 131072)
#define PR_RM   (PR_LAT + 1024)
#define PR_END  (PR_RM + 128)
__global__ __launch_bounds__(256) void prep_kernel(
    const float* __restrict__ Wkv, const float* __restrict__ Wq,
    const float* __restrict__ Wout, const float* __restrict__ latents)
{
    int id = blockIdx.x * 256 + threadIdx.x;
    if (id < PR_WKV) {
        float4 v = reinterpret_cast<const float4*>(Wkv)[id];
        reinterpret_cast<uint2*>(g_wkvh)[id] = hi_pack_h(v);
    } else if (id < PR_WQ) {
        int i = id - PR_WKV;
        float4 v = reinterpret_cast<const float4*>(Wq)[i];
        reinterpret_cast<uint2*>(g_wqh)[i] = hi_pack_h(v);
    } else if (id < PR_WOUT) {
        int i = id - PR_WQ;
        float4 v = reinterpret_cast<const float4*>(Wout)[i];
        reinterpret_cast<uint2*>(g_wouth)[i] = hi_pack_h(v);
    } else if (id < PR_LAT) {
        int i = id - PR_WOUT;
        float4 v = reinterpret_cast<const float4*>(latents)[i];
        reinterpret_cast<uint2*>(g_lath)[i] = hi_pack_h(v);
        reinterpret_cast<uint2*>(g_latl)[i] = lo_pack_h(v);
    } else if (id < PR_RM) {
        g_rmax_ord[id - PR_LAT] = 0u;
    } else if (id < PR_END) {
        g_losspart[id - PR_RM] = 0.f;
    }
}

// ==================== fp16 GEMM, cp.async + fragment double-buffering ======
#define A_TILE     16384
#define STAGE_B    49152
#define GSMEM_B    147456

__global__ __launch_bounds__(256, 1) void gemm16_kernel(
    const __half* __restrict__ Ah, const __half* __restrict__ Al,
    const __half* __restrict__ Bh, float* __restrict__ C,
    int Ng, int Kg, float alpha)
{
    extern __shared__ char sm[];
    const uint32_t smb = smem_u32(sm);
    const int tid  = threadIdx.x;
    const int lane = tid & 31;
    const int wid  = tid >> 5;
    const int wm   = wid >> 2;
    const int wn   = wid & 3;
    const int row0 = blockIdx.y * 128;
    const int col0 = blockIdx.x * 128;

    float acc[4][4][4];
#pragma unroll
    for (int mt = 0; mt < 4; mt++)
#pragma unroll
        for (int nt = 0; nt < 4; nt++)
#pragma unroll
            for (int e = 0; e < 4; e++) acc[mt][nt][e] = 0.f;

    // fragment double buffers
    uint32_t fah[2][4][4], fal[2][4][4], fbh[2][4][2];

#define LOAD(i) do { \
    const int s_ = (i) % 3; \
    const uint32_t sb_ = smb + s_ * STAGE_B; \
    const int k0_ = (i) * 64; \
    _Pragma("unroll") \
    for (int c_ = 0; c_ < 4; c_++) { \
        int id_ = tid + c_ * 256; \
        int r_ = id_ >> 3, c16_ = id_ & 7; \
        uint32_t doff_ = SW128((uint32_t)(r_ * 128 + c16_ * 16)); \
        CP_ASYNC16(sb_ + doff_,              (const void*)&Ah[(size_t)(row0 + r_) * Kg + k0_ + c16_ * 8]); \
        CP_ASYNC16(sb_ + A_TILE + doff_,     (const void*)&Al[(size_t)(row0 + r_) * Kg + k0_ + c16_ * 8]); \
        CP_ASYNC16(sb_ + 2 * A_TILE + doff_, (const void*)&Bh[(size_t)(col0 + r_) * Kg + k0_ + c16_ * 8]); \
    } } while (0)

// load register fragments for k-step ks of smem stage sb_ into buffer fb
#define FRAG(sb_, ks, fb) do { \
    _Pragma("unroll") \
    for (int mt = 0; mt < 4; mt++) { \
        uint32_t r_ = wm * 64 + mt * 16 + (lane & 15); \
        uint32_t off_ = SW128(r_ * 128 + (ks) * 32 + (lane >> 4) * 16); \
        LDMX4(fah[fb][mt], (sb_) + off_); \
        LDMX4(fal[fb][mt], (sb_) + A_TILE + off_); \
    } \
    _Pragma("unroll") \
    for (int nt = 0; nt < 4; nt++) { \
        uint32_t n_ = wn * 32 + nt * 8 + (lane >> 2); \
        fbh[fb][nt][0] = lds32((sb_) + 2 * A_TILE + SW128(n_ * 128 + (ks) * 32 + (lane & 3) * 4)); \
        fbh[fb][nt][1] = lds32((sb_) + 2 * A_TILE + SW128(n_ * 128 + (ks) * 32 + 16 + (lane & 3) * 4)); \
    } } while (0)

#define MMAS(fb) do { \
    _Pragma("unroll") \
    for (int mt = 0; mt < 4; mt++) \
    _Pragma("unroll") \
    for (int nt = 0; nt < 4; nt++) { \
        MMA_F16(acc[mt][nt], fah[fb][mt], fbh[fb][nt]); \
        MMA_F16(acc[mt][nt], fal[fb][mt], fbh[fb][nt]); \
    } } while (0)

    const int nk = Kg >> 6;
    LOAD(0); CP_COMMIT;
    LOAD(1); CP_COMMIT;
    for (int i = 0; i < nk; i++) {
        if (i + 1 < nk) { CP_WAIT1; } else { CP_WAIT0; }
        __syncthreads();
        if (i + 2 < nk) { LOAD(i + 2); CP_COMMIT; }
        const uint32_t sb_ = smb + (i % 3) * STAGE_B;
        FRAG(sb_, 0, 0);
#pragma unroll
        for (int ks = 0; ks < 4; ks++) {
            if (ks < 3) FRAG(sb_, ks + 1, (ks + 1) & 1);
            MMAS(ks & 1);
        }
    }

#pragma unroll
    for (int mt = 0; mt < 4; mt++) {
        int r = row0 + wm * 64 + mt * 16 + (lane >> 2);
#pragma unroll
        for (int nt = 0; nt < 4; nt++) {
            int c = col0 + wn * 32 + nt * 8 + (lane & 3) * 2;
            float2 v0 = make_float2(alpha * acc[mt][nt][0], alpha * acc[mt][nt][1]);
            float2 v1 = make_float2(alpha * acc[mt][nt][2], alpha * acc[mt][nt][3]);
            *reinterpret_cast<float2*>(&C[(size_t)r * Ng + c]) = v0;
            *reinterpret_cast<float2*>(&C[(size_t)(r + 8) * Ng + c]) = v1;
        }
    }
#undef LOAD
#undef FRAG
#undef MMAS
}

// ==================== sim + mask + rowmax (8x8 blocking) ==================
__global__ __launch_bounds__(128) void sim_kernel(const int* __restrict__ mask)
{
    const int bh = blockIdx.y;
    const int b  = bh >> 4;
    const int h  = bh & 15;
    const int n0 = blockIdx.x * 128;
    const int tid = threadIdx.x;
    const int ty = tid >> 4;
    const int tx = tid & 15;

    __shared__ float qs[64][65];
    __shared__ float ks[128][65];
    __shared__ float redm[64][17];

    for (int s = tid; s < 1024; s += 128) {
        int r = s >> 4, c4 = s & 15;
        float4 v = *reinterpret_cast<const float4*>(
            &g_q[(size_t)(b * M_ + r) * INNER_ + h * DH_ + c4 * 4]);
        qs[r][c4 * 4 + 0] = v.x; qs[r][c4 * 4 + 1] = v.y;
        qs[r][c4 * 4 + 2] = v.z; qs[r][c4 * 4 + 3] = v.w;
    }
    for (int s = tid; s < 2048; s += 128) {
        int r = s >> 4, c4 = s & 15;
        float4 v = *reinterpret_cast<const float4*>(
            &g_kv[((size_t)b * N_ + n0 + r) * KV2_ + h * DH_ + c4 * 4]);
        ks[r][c4 * 4 + 0] = v.x; ks[r][c4 * 4 + 1] = v.y;
        ks[r][c4 * 4 + 2] = v.z; ks[r][c4 * 4 + 3] = v.w;
    }
    __syncthreads();

    float acc[8][8];
#pragma unroll
    for (int u = 0; u < 8; u++)
#pragma unroll
        for (int v = 0; v < 8; v++) acc[u][v] = 0.f;

#pragma unroll 4
    for (int d = 0; d < 64; d++) {
        float a[8], c[8];
#pragma unroll
        for (int u = 0; u < 8; u++) a[u] = qs[ty * 8 + u][d];
#pragma unroll
        for (int v = 0; v < 8; v++) c[v] = ks[tx * 8 + v][d];
#pragma unroll
        for (int u = 0; u < 8; u++)
#pragma unroll
            for (int v = 0; v < 8; v++) acc[u][v] += a[u] * c[v];
    }

    int mk[8];
#pragma unroll
    for (int v = 0; v < 8; v++) mk[v] = mask[b * N_ + n0 + tx * 8 + v];

#pragma unroll
    for (int u = 0; u < 8; u++) {
        int i = ty * 8 + u;
        float rm = -FLT_MAX;
        float row[8];
#pragma unroll
        for (int v = 0; v < 8; v++) {
            float val = (mk[v] != 0) ? -FLT_MAX : acc[u][v];
            row[v] = val;
            rm = fmaxf(rm, val);
        }
        float4* dst = reinterpret_cast<float4*>(
            &g_sim[((size_t)bh * M_ + i) * N_ + n0 + tx * 8]);
        dst[0] = make_float4(row[0], row[1], row[2], row[3]);
        dst[1] = make_float4(row[4], row[5], row[6], row[7]);
        redm[i][tx] = rm;
    }
    __syncthreads();
    if (tid < 64) {
        float m = redm[tid][0];
#pragma unroll
        for (int t = 1; t < 16; t++) m = fmaxf(m, redm[tid][t]);
        atomicMax(&g_rmax_ord[bh * M_ + tid], f2o(m));
    }
}

// ==================== pv chunk ============================================
__global__ __launch_bounds__(256) void pv_chunk_kernel(const int* __restrict__ mask)
{
    const int ch = blockIdx.x;
    const int bh = blockIdx.y;
    const int b  = bh >> 4;
    const int h  = bh & 15;
    const int tid = threadIdx.x;

    __shared__ float ps[64][65];
    __shared__ float vs[64][65];
    __shared__ float rs[64];
    __shared__ float colred[2][4][64];
    __shared__ float lred[64];

    if (tid < 64) rs[tid] = o2f(g_rmax_ord[bh * M_ + tid]);
    __syncthreads();

    const int cq = tid >> 6;
    const int ccol = tid & 63;
    const int ty = tid >> 4, tx = tid & 15;
    float acc[4][4];
#pragma unroll
    for (int u = 0; u < 4; u++)
#pragma unroll
        for (int c = 0; c < 4; c++) acc[u][c] = 0.f;
    float lossloc = 0.f;
    float denloc = 0.f;

    const int jt0 = ch * (64 / NCH_);
    for (int jt = jt0; jt < jt0 + 64 / NCH_; jt++) {
        const int j0 = jt * 64;
        float st = 0.f, st2 = 0.f;
#pragma unroll 4
        for (int k = 0; k < 16; k++) {
            int r = cq + 4 * k;
            float sv = g_sim[((size_t)bh * M_ + r) * N_ + j0 + ccol];
            float t = sv - rs[r];
            ps[r][ccol] = __expf(t);
            st += t; st2 += t * t;
            vs[r][ccol] = g_kv[((size_t)b * N_ + j0 + r) * KV2_ + INNER_ + h * DH_ + ccol];
        }
        colred[0][cq][ccol] = st;
        colred[1][cq][ccol] = st2;
        __syncthreads();

        if (tid < 64) {
            if (mask[b * N_ + j0 + tid] == 0) {
                float s  = colred[0][0][tid] + colred[0][1][tid] + colred[0][2][tid] + colred[0][3][tid];
                float ss = colred[1][0][tid] + colred[1][1][tid] + colred[1][2][tid] + colred[1][3][tid];
                float var = (ss - s * s * (1.0f / 64.f)) * (1.0f / 63.f);
                float sd  = sqrtf(var + 1e-4f);
                lossloc += fmaxf(1.0f - sd, 0.0f);
            }
            float sde = 0.f;
#pragma unroll 8
            for (int j = 0; j < 64; j++) sde += ps[tid][j];
            denloc += sde;
        }
#pragma unroll 4
        for (int j = 0; j < 64; j++) {
            float pv[4], vv[4];
#pragma unroll
            for (int u = 0; u < 4; u++) pv[u] = ps[ty + 16 * u][j];
#pragma unroll
            for (int c = 0; c < 4; c++) vv[c] = vs[j][tx + 16 * c];
#pragma unroll
            for (int u = 0; u < 4; u++)
#pragma unroll
                for (int c = 0; c < 4; c++) acc[u][c] += pv[u] * vv[c];
        }
        __syncthreads();
    }

    float* pvb = &g_pvpart[((size_t)bh * NCH_ + ch) * M_ * DH_];
#pragma unroll
    for (int u = 0; u < 4; u++) {
        int i = ty + 16 * u;
#pragma unroll
        for (int c = 0; c < 4; c++) pvb[i * DH_ + tx + 16 * c] = acc[u][c];
    }
    if (tid < 64) g_denpart[(bh * NCH_ + ch) * M_ + tid] = denloc;

    if (tid < 64) lred[tid] = lossloc;
    __syncthreads();
    if (tid < 32) lred[tid] += lred[tid + 32];
    __syncthreads();
    if (tid == 0) {
        float s = 0.f;
#pragma unroll
        for (int t = 0; t < 32; t++) s += lred[t];
        g_losschunk[bh * NCH_ + ch] = s;
    }
}

// ==================== pv combine ==========================================
__global__ __launch_bounds__(256) void pv_combine_kernel()
{
    const int bh = blockIdx.x;
    const int b  = bh >> 4;
    const int h  = bh & 15;
    const int tid = threadIdx.x;

    __shared__ float dinv[64];
    if (tid < 64) {
        float d = 0.f;
#pragma unroll
        for (int c = 0; c < NCH_; c++) d += g_denpart[(bh * NCH_ + c) * M_ + tid];
        dinv[tid] = 1.0f / d;
    }
    if (tid == 64) {
        float s = 0.f;
#pragma unroll
        for (int c = 0; c < NCH_; c++) s += g_losschunk[bh * NCH_ + c];
        g_losspart[bh] = s;
    }
    __syncthreads();

    const float* pvb = &g_pvpart[(size_t)bh * NCH_ * M_ * DH_];
    for (int idx = tid; idx < M_ * DH_; idx += 256) {
        int i = idx >> 6, d = idx & 63;
        float s = 0.f;
#pragma unroll
        for (int c = 0; c < NCH_; c++) s += pvb[c * M_ * DH_ + idx];
        g_attnout[((size_t)b * M_ + i) * INNER_ + h * DH_ + d] = s * dinv[i];
    }
}

__global__ __launch_bounds__(128) void loss_final_kernel(float* __restrict__ out, int idx)
{
    __shared__ float red[128];
    red[threadIdx.x] = g_losspart[threadIdx.x];
    __syncthreads();
    for (int t = 64; t > 0; t >>= 1) {
        if (threadIdx.x < t) red[threadIdx.x] += red[threadIdx.x + t];
        __syncthreads();
    }
    if (threadIdx.x == 0) out[idx] = red[0] * (1.0f / (float)(B_ * H_ * N_));
}

// ==================== launch ==============================================
extern "C" void kernel_launch(void* const* d_in, const int* in_sizes, int n_in,
                              void* d_out, int out_size)
{
    const float* x       = (const float*)d_in[0];
    const float* latents = (const float*)d_in[1];
    const int*   mask    = (const int*)d_in[2];
    const float* Wq      = (const float*)d_in[3];
    const float* Wkv     = (const float*)d_in[4];
    const float* Wout    = (const float*)d_in[5];
    float*       out     = (float*)d_out;

    cudaFuncSetAttribute(gemm16_kernel, cudaFuncAttributeMaxDynamicSharedMemorySize, GSMEM_B);

    void *pxh, *pxl, *pkvh, *pqh, *poh, *plh, *pll, *pah, *pal;
    void *pq, *pattn, *pkv;
    cudaGetSymbolAddress(&pxh, g_xh);   cudaGetSymbolAddress(&pxl, g_xl);
    cudaGetSymbolAddress(&pkvh, g_wkvh);
    cudaGetSymbolAddress(&pqh, g_wqh);  cudaGetSymbolAddress(&poh, g_wouth);
    cudaGetSymbolAddress(&plh, g_lath); cudaGetSymbolAddress(&pll, g_latl);
    cudaGetSymbolAddress(&pah, g_ah);   cudaGetSymbolAddress(&pal, g_al);
    cudaGetSymbolAddress(&pq, g_q);
    cudaGetSymbolAddress(&pkv, g_kv);
    cudaGetSymbolAddress(&pattn, g_attnout);

    // L1: split x -> fp16 hi/lo
    split2_kernel<<<(B_ * N_ * DIM_ / 4 + 255) / 256, 256>>>(
        x, (__half*)pxh, (__half*)pxl, B_ * N_ * DIM_ / 4);

    // L2: split weights + latents, init rmax/loss
    prep_kernel<<<(PR_END + 255) / 256, 256>>>(Wkv, Wq, Wout, latents);

    // L3: q = latents @ Wq^T * scale
    gemm16_kernel<<<dim3(INNER_ / 128, (B_ * M_) / 128), 256, GSMEM_B>>>(
        (const __half*)plh, (const __half*)pll, (const __half*)pqh,
        (float*)pq, INNER_, DIM_, 0.125f);

    // L4: kv = x @ Wkv^T   (profiled launch)
    gemm16_kernel<<<dim3(KV2_ / 128, (B_ * N_) / 128), 256, GSMEM_B>>>(
        (const __half*)pxh, (const __half*)pxl, (const __half*)pkvh,
        (float*)pkv, KV2_, DIM_, 1.0f);

    // L5: sim + mask + rowmax
    sim_kernel<<<dim3(N_ / 128, B_ * H_), 128>>>(mask);

    // L6: pv chunks
    pv_chunk_kernel<<<dim3(NCH_, B_ * H_), 256>>>(mask);

    // L7: combine
    pv_combine_kernel<<<B_ * H_, 256>>>();

    // L8: split attn output
    split2_kernel<<<(B_ * M_ * INNER_ / 4 + 255) / 256, 256>>>(
        (const float*)pattn, (__half*)pah, (__half*)pal, B_ * M_ * INNER_ / 4);

    // L9: loss finalize
    loss_final_kernel<<<1, 128>>>(out, out_size - 1);

    // L10: out = attn_out @ Wout^T
    gemm16_kernel<<<dim3(DIM_ / 128, (B_ * M_) / 128), 256, GSMEM_B>>>(
        (const __half*)pah, (const __half*)pal, (const __half*)poh,
        out, DIM_, INNER_, 1.0f);
}

// round 9
// speedup vs baseline: 4.3508x; 1.1149x over previous
#include <cuda_runtime.h>
#include <cuda_fp16.h>
#include <cfloat>
#include <math.h>
#include <cstdint>

#define B_   8
#define N_   4096
#define M_   64
#define DIM_ 1024
#define H_   16
#define DH_  64
#define INNER_ 1024
#define KV2_  2048
#define NCH_  4

// ==================== scratch =============================================
__device__ float    g_q[B_ * M_ * INNER_];
__device__ float    g_kv[(size_t)B_ * N_ * KV2_];
__device__ float    g_sim[(size_t)B_ * H_ * M_ * N_];
__device__ unsigned g_rmax_ord[B_ * H_ * M_];
__device__ float    g_attnout[B_ * M_ * INNER_];
__device__ float    g_losspart[B_ * H_];
__device__ float    g_pvpart[B_ * H_ * NCH_ * M_ * DH_];
__device__ float    g_denpart[B_ * H_ * NCH_ * M_];
__device__ float    g_losschunk[B_ * H_ * NCH_];

// fp16 split buffers
__device__ __half g_xh[(size_t)B_ * N_ * DIM_];
__device__ __half g_xl[(size_t)B_ * N_ * DIM_];
__device__ __half g_wkvh[KV2_ * DIM_];
__device__ __half g_wqh[INNER_ * DIM_];
__device__ __half g_wouth[DIM_ * INNER_];
__device__ __half g_lath[B_ * M_ * DIM_];
__device__ __half g_latl[B_ * M_ * DIM_];
__device__ __half g_ah[B_ * M_ * INNER_];
__device__ __half g_al[B_ * M_ * INNER_];
__device__ __half g_kvh16[(size_t)B_ * N_ * KV2_];   // fp16 copy of kv (K2 epilogue)
__device__ __half g_qh16[B_ * M_ * INNER_];
__device__ __half g_ql16[B_ * M_ * INNER_];

// ==================== helpers =============================================
__device__ __forceinline__ uint32_t smem_u32(const void* p) {
    uint32_t a;
    asm("{ .reg .u64 t; cvta.to.shared.u64 t, %1; cvt.u32.u64 %0, t; }" : "=r"(a) : "l"(p));
    return a;
}
__device__ __forceinline__ uint32_t lds32(uint32_t a) {
    uint32_t v;
    asm volatile("ld.shared.b32 %0, [%1];" : "=r"(v) : "r"(a));
    return v;
}
#define LDMX4(r, addr) \
    asm volatile("ldmatrix.sync.aligned.m8n8.x4.shared.b16 {%0,%1,%2,%3}, [%4];" \
        : "=r"((r)[0]), "=r"((r)[1]), "=r"((r)[2]), "=r"((r)[3]) : "r"(addr))
#define MMA_F16(c, a, b) \
    asm volatile("mma.sync.aligned.m16n8k16.row.col.f32.f16.f16.f32 " \
        "{%0,%1,%2,%3}, {%4,%5,%6,%7}, {%8,%9}, {%0,%1,%2,%3};" \
        : "+f"((c)[0]), "+f"((c)[1]), "+f"((c)[2]), "+f"((c)[3]) \
        : "r"((a)[0]), "r"((a)[1]), "r"((a)[2]), "r"((a)[3]), "r"((b)[0]), "r"((b)[1]))
#define MMA_F16_2(c, a0, a1, a2, a3, b) \
    MMA_F16(c, a0, b)
#define CP_ASYNC16(dst, src) \
    asm volatile("cp.async.cg.shared.global [%0], [%1], 16;" :: "r"(dst), "l"(src) : "memory")
#define CP_COMMIT asm volatile("cp.async.commit_group;" ::: "memory")
#define CP_WAIT1  asm volatile("cp.async.wait_group 1;" ::: "memory")
#define CP_WAIT0  asm volatile("cp.async.wait_group 0;" ::: "memory")
#define SW128(off) ((off) ^ (((off) >> 3) & 0x70))

__device__ __forceinline__ uint2 hi_pack_h(float4 v) {
    __half2 p0(__float2half_rn(v.x), __float2half_rn(v.y));
    __half2 p1(__float2half_rn(v.z), __float2half_rn(v.w));
    uint2 r;
    r.x = *reinterpret_cast<uint32_t*>(&p0);
    r.y = *reinterpret_cast<uint32_t*>(&p1);
    return r;
}
__device__ __forceinline__ uint2 lo_pack_h(float4 v) {
    float4 l;
    l.x = v.x - __half2float(__float2half_rn(v.x));
    l.y = v.y - __half2float(__float2half_rn(v.y));
    l.z = v.z - __half2float(__float2half_rn(v.z));
    l.w = v.w - __half2float(__float2half_rn(v.w));
    return hi_pack_h(l);
}
__device__ __forceinline__ unsigned f2o(float f) {
    unsigned b = __float_as_uint(f);
    return (b & 0x80000000u) ? ~b : (b | 0x80000000u);
}
__device__ __forceinline__ float o2f(unsigned u) {
    return __uint_as_float((u & 0x80000000u) ? (u ^ 0x80000000u) : ~u);
}

// ==================== split kernels =======================================
__global__ __launch_bounds__(256) void split2_kernel(
    const float* __restrict__ src, __half* __restrict__ h, __half* __restrict__ l, int n4)
{
    int i = blockIdx.x * 256 + threadIdx.x;
    if (i >= n4) return;
    float4 v = reinterpret_cast<const float4*>(src)[i];
    reinterpret_cast<uint2*>(h)[i] = hi_pack_h(v);
    reinterpret_cast<uint2*>(l)[i] = lo_pack_h(v);
}

#define PR_WKV  524288
#define PR_WQ   (PR_WKV + 262144)
#define PR_WOUT (PR_WQ + 262144)
#define PR_LAT  (PR_WOUT + 131072)
#define PR_RM   (PR_LAT + 1024)
#define PR_END  (PR_RM + 128)
__global__ __launch_bounds__(256) void prep_kernel(
    const float* __restrict__ Wkv, const float* __restrict__ Wq,
    const float* __restrict__ Wout, const float* __restrict__ latents)
{
    int id = blockIdx.x * 256 + threadIdx.x;
    if (id < PR_WKV) {
        float4 v = reinterpret_cast<const float4*>(Wkv)[id];
        reinterpret_cast<uint2*>(g_wkvh)[id] = hi_pack_h(v);
    } else if (id < PR_WQ) {
        int i = id - PR_WKV;
        float4 v = reinterpret_cast<const float4*>(Wq)[i];
        reinterpret_cast<uint2*>(g_wqh)[i] = hi_pack_h(v);
    } else if (id < PR_WOUT) {
        int i = id - PR_WQ;
        float4 v = reinterpret_cast<const float4*>(Wout)[i];
        reinterpret_cast<uint2*>(g_wouth)[i] = hi_pack_h(v);
    } else if (id < PR_LAT) {
        int i = id - PR_WOUT;
        float4 v = reinterpret_cast<const float4*>(latents)[i];
        reinterpret_cast<uint2*>(g_lath)[i] = hi_pack_h(v);
        reinterpret_cast<uint2*>(g_latl)[i] = lo_pack_h(v);
    } else if (id < PR_RM) {
        g_rmax_ord[id - PR_LAT] = 0u;
    } else if (id < PR_END) {
        g_losspart[id - PR_RM] = 0.f;
    }
}

// ==================== fp16 GEMM, cp.async 3-stage pipeline ================
#define A_TILE     16384
#define STAGE_B    49152
#define GSMEM_B    147456

__global__ __launch_bounds__(256, 1) void gemm16_kernel(
    const __half* __restrict__ Ah, const __half* __restrict__ Al,
    const __half* __restrict__ Bh, float* __restrict__ C,
    __half* __restrict__ Ch,         // optional fp16 copy of output
    int Ng, int Kg, float alpha)
{
    extern __shared__ char sm[];
    const uint32_t smb = smem_u32(sm);
    const int tid  = threadIdx.x;
    const int lane = tid & 31;
    const int wid  = tid >> 5;
    const int wm   = wid >> 2;
    const int wn   = wid & 3;
    const int row0 = blockIdx.y * 128;
    const int col0 = blockIdx.x * 128;

    float acc[4][4][4];
#pragma unroll
    for (int mt = 0; mt < 4; mt++)
#pragma unroll
        for (int nt = 0; nt < 4; nt++)
#pragma unroll
            for (int e = 0; e < 4; e++) acc[mt][nt][e] = 0.f;

#define LOAD(i) do { \
    const int s_ = (i) % 3; \
    const uint32_t sb_ = smb + s_ * STAGE_B; \
    const int k0_ = (i) * 64; \
    _Pragma("unroll") \
    for (int c_ = 0; c_ < 4; c_++) { \
        int id_ = tid + c_ * 256; \
        int r_ = id_ >> 3, c16_ = id_ & 7; \
        uint32_t doff_ = SW128((uint32_t)(r_ * 128 + c16_ * 16)); \
        CP_ASYNC16(sb_ + doff_,              (const void*)&Ah[(size_t)(row0 + r_) * Kg + k0_ + c16_ * 8]); \
        CP_ASYNC16(sb_ + A_TILE + doff_,     (const void*)&Al[(size_t)(row0 + r_) * Kg + k0_ + c16_ * 8]); \
        CP_ASYNC16(sb_ + 2 * A_TILE + doff_, (const void*)&Bh[(size_t)(col0 + r_) * Kg + k0_ + c16_ * 8]); \
    } } while (0)

#define COMPUTE(s) do { \
    const uint32_t sb_ = smb + (s) * STAGE_B; \
    _Pragma("unroll") \
    for (int ks = 0; ks < 4; ks++) { \
        uint32_t ah[4][4], al[4][4], bh[4][2]; \
        _Pragma("unroll") \
        for (int mt = 0; mt < 4; mt++) { \
            uint32_t r_ = wm * 64 + mt * 16 + (lane & 15); \
            uint32_t off_ = SW128(r_ * 128 + ks * 32 + (lane >> 4) * 16); \
            LDMX4(ah[mt], sb_ + off_); \
            LDMX4(al[mt], sb_ + A_TILE + off_); \
        } \
        _Pragma("unroll") \
        for (int nt = 0; nt < 4; nt++) { \
            uint32_t n_ = wn * 32 + nt * 8 + (lane >> 2); \
            bh[nt][0] = lds32(sb_ + 2 * A_TILE + SW128(n_ * 128 + ks * 32 + (lane & 3) * 4)); \
            bh[nt][1] = lds32(sb_ + 2 * A_TILE + SW128(n_ * 128 + ks * 32 + 16 + (lane & 3) * 4)); \
        } \
        _Pragma("unroll") \
        for (int mt = 0; mt < 4; mt++) \
        _Pragma("unroll") \
        for (int nt = 0; nt < 4; nt++) { \
            MMA_F16(acc[mt][nt], ah[mt], bh[nt]); \
            MMA_F16(acc[mt][nt], al[mt], bh[nt]); \
        } \
    } } while (0)

    const int nk = Kg >> 6;
    LOAD(0); CP_COMMIT;
    LOAD(1); CP_COMMIT;
    for (int i = 0; i < nk; i++) {
        if (i + 1 < nk) { CP_WAIT1; } else { CP_WAIT0; }
        __syncthreads();
        if (i + 2 < nk) { LOAD(i + 2); CP_COMMIT; }
        COMPUTE(i % 3);
    }

#pragma unroll
    for (int mt = 0; mt < 4; mt++) {
        int r = row0 + wm * 64 + mt * 16 + (lane >> 2);
#pragma unroll
        for (int nt = 0; nt < 4; nt++) {
            int c = col0 + wn * 32 + nt * 8 + (lane & 3) * 2;
            float2 v0 = make_float2(alpha * acc[mt][nt][0], alpha * acc[mt][nt][1]);
            float2 v1 = make_float2(alpha * acc[mt][nt][2], alpha * acc[mt][nt][3]);
            *reinterpret_cast<float2*>(&C[(size_t)r * Ng + c]) = v0;
            *reinterpret_cast<float2*>(&C[(size_t)(r + 8) * Ng + c]) = v1;
            if (Ch) {
                __half2 h0 = __floats2half2_rn(v0.x, v0.y);
                __half2 h1 = __floats2half2_rn(v1.x, v1.y);
                *reinterpret_cast<__half2*>(&Ch[(size_t)r * Ng + c]) = h0;
                *reinterpret_cast<__half2*>(&Ch[(size_t)(r + 8) * Ng + c]) = h1;
            }
        }
    }
#undef LOAD
#undef COMPUTE
}

// ==================== sim via mma.sync + mask + rowmax ====================
// Per block: rows = 64 latents of (b,h), cols = 128 keys. K=64 single slab.
// q fp16 hi/lo (exact), k fp16 (rounded). 8 warps (2x4), warp tile 32x32.
__global__ __launch_bounds__(256) void sim_mma_kernel(const int* __restrict__ mask)
{
    const int bh = blockIdx.y;
    const int b  = bh >> 4;
    const int h  = bh & 15;
    const int n0 = blockIdx.x * 128;
    const int tid = threadIdx.x;
    const int lane = tid & 31;
    const int wid  = tid >> 5;
    const int wm   = wid >> 2;    // 0..1
    const int wn   = wid & 3;     // 0..3

    __shared__ __half sqh[64 * 64];   // 8KB, SW128
    __shared__ __half sql[64 * 64];   // 8KB
    __shared__ __half skh[128 * 64];  // 16KB
    __shared__ int    msk[128];
    __shared__ float  redm[64][5];

    const uint32_t bqh = smem_u32(sqh);
    const uint32_t bql = smem_u32(sql);
    const uint32_t bkh = smem_u32(skh);

    // async loads (row = 64 halves = 128B)
#pragma unroll
    for (int c = 0; c < 2; c++) {
        int id = tid + c * 256;          // 0..511
        int r = id >> 3, c16 = id & 7;
        uint32_t off = SW128((uint32_t)(r * 128 + c16 * 16));
        CP_ASYNC16(bqh + off, (const void*)&g_qh16[(size_t)(b * M_ + r) * INNER_ + h * DH_ + c16 * 8]);
        CP_ASYNC16(bql + off, (const void*)&g_ql16[(size_t)(b * M_ + r) * INNER_ + h * DH_ + c16 * 8]);
    }
#pragma unroll
    for (int c = 0; c < 4; c++) {
        int id = tid + c * 256;          // 0..1023
        int r = id >> 3, c16 = id & 7;
        uint32_t off = SW128((uint32_t)(r * 128 + c16 * 16));
        CP_ASYNC16(bkh + off, (const void*)&g_kvh16[((size_t)b * N_ + n0 + r) * KV2_ + h * DH_ + c16 * 8]);
    }
    CP_COMMIT;
    if (tid < 128) msk[tid] = mask[b * N_ + n0 + tid];
    CP_WAIT0;
    __syncthreads();

    float acc[2][4][4];
#pragma unroll
    for (int mt = 0; mt < 2; mt++)
#pragma unroll
        for (int nt = 0; nt < 4; nt++)
#pragma unroll
            for (int e = 0; e < 4; e++) acc[mt][nt][e] = 0.f;

#pragma unroll
    for (int ks = 0; ks < 4; ks++) {
        uint32_t ah[2][4], al[2][4], bf[4][2];
#pragma unroll
        for (int mt = 0; mt < 2; mt++) {
            uint32_t r_ = wm * 32 + mt * 16 + (lane & 15);
            uint32_t off = SW128(r_ * 128 + ks * 32 + (lane >> 4) * 16);
            LDMX4(ah[mt], bqh + off);
            LDMX4(al[mt], bql + off);
        }
#pragma unroll
        for (int nt = 0; nt < 4; nt++) {
            uint32_t n_ = wn * 32 + nt * 8 + (lane >> 2);
            bf[nt][0] = lds32(bkh + SW128(n_ * 128 + ks * 32 + (lane & 3) * 4));
            bf[nt][1] = lds32(bkh + SW128(n_ * 128 + ks * 32 + 16 + (lane & 3) * 4));
        }
#pragma unroll
        for (int mt = 0; mt < 2; mt++)
#pragma unroll
            for (int nt = 0; nt < 4; nt++) {
                MMA_F16(acc[mt][nt], ah[mt], bf[nt]);
                MMA_F16(acc[mt][nt], al[mt], bf[nt]);
            }
    }

    // epilogue: mask, store, rowmax
#pragma unroll
    for (int mt = 0; mt < 2; mt++) {
        int r = wm * 32 + mt * 16 + (lane >> 2);
        float m0 = -FLT_MAX, m1 = -FLT_MAX;
#pragma unroll
        for (int nt = 0; nt < 4; nt++) {
            int c = wn * 32 + nt * 8 + (lane & 3) * 2;
            float v0 = msk[c]     ? -FLT_MAX : acc[mt][nt][0];
            float v1 = msk[c + 1] ? -FLT_MAX : acc[mt][nt][1];
            float v2 = msk[c]     ? -FLT_MAX : acc[mt][nt][2];
            float v3 = msk[c + 1] ? -FLT_MAX : acc[mt][nt][3];
            *reinterpret_cast<float2*>(&g_sim[((size_t)bh * M_ + r) * N_ + n0 + c]) = make_float2(v0, v1);
            *reinterpret_cast<float2*>(&g_sim[((size_t)bh * M_ + r + 8) * N_ + n0 + c]) = make_float2(v2, v3);
            m0 = fmaxf(m0, fmaxf(v0, v1));
            m1 = fmaxf(m1, fmaxf(v2, v3));
        }
#pragma unroll
        for (int s = 1; s < 4; s <<= 1) {
            m0 = fmaxf(m0, __shfl_xor_sync(0xffffffffu, m0, s));
            m1 = fmaxf(m1, __shfl_xor_sync(0xffffffffu, m1, s));
        }
        if ((lane & 3) == 0) {
            redm[r][wn]     = m0;
            redm[r + 8][wn] = m1;
        }
    }
    __syncthreads();
    if (tid < 64) {
        float m = fmaxf(fmaxf(redm[tid][0], redm[tid][1]), fmaxf(redm[tid][2], redm[tid][3]));
        atomicMax(&g_rmax_ord[bh * M_ + tid], f2o(m));
    }
}

// ==================== pv chunk ============================================
__global__ __launch_bounds__(256) void pv_chunk_kernel(const int* __restrict__ mask)
{
    const int ch = blockIdx.x;
    const int bh = blockIdx.y;
    const int b  = bh >> 4;
    const int h  = bh & 15;
    const int tid = threadIdx.x;

    __shared__ float ps[64][65];
    __shared__ float vs[64][65];
    __shared__ float rs[64];
    __shared__ float colred[2][4][64];
    __shared__ float lred[64];

    if (tid < 64) rs[tid] = o2f(g_rmax_ord[bh * M_ + tid]);
    __syncthreads();

    const int cq = tid >> 6;
    const int ccol = tid & 63;
    const int ty = tid >> 4, tx = tid & 15;
    float acc[4][4];
#pragma unroll
    for (int u = 0; u < 4; u++)
#pragma unroll
        for (int c = 0; c < 4; c++) acc[u][c] = 0.f;
    float lossloc = 0.f;
    float denloc = 0.f;

    const int jt0 = ch * (64 / NCH_);
    for (int jt = jt0; jt < jt0 + 64 / NCH_; jt++) {
        const int j0 = jt * 64;
        float st = 0.f, st2 = 0.f;
#pragma unroll 4
        for (int k = 0; k < 16; k++) {
            int r = cq + 4 * k;
            float sv = g_sim[((size_t)bh * M_ + r) * N_ + j0 + ccol];
            float t = sv - rs[r];
            ps[r][ccol] = __expf(t);
            st += t; st2 += t * t;
            vs[r][ccol] = g_kv[((size_t)b * N_ + j0 + r) * KV2_ + INNER_ + h * DH_ + ccol];
        }
        colred[0][cq][ccol] = st;
        colred[1][cq][ccol] = st2;
        __syncthreads();

        if (tid < 64) {
            if (mask[b * N_ + j0 + tid] == 0) {
                float s  = colred[0][0][tid] + colred[0][1][tid] + colred[0][2][tid] + colred[0][3][tid];
                float ss = colred[1][0][tid] + colred[1][1][tid] + colred[1][2][tid] + colred[1][3][tid];
                float var = (ss - s * s * (1.0f / 64.f)) * (1.0f / 63.f);
                float sd  = sqrtf(var + 1e-4f);
                lossloc += fmaxf(1.0f - sd, 0.0f);
            }
            float sde = 0.f;
#pragma unroll 8
            for (int j = 0; j < 64; j++) sde += ps[tid][j];
            denloc += sde;
        }
#pragma unroll 4
        for (int j = 0; j < 64; j++) {
            float pv[4], vv[4];
#pragma unroll
            for (int u = 0; u < 4; u++) pv[u] = ps[ty + 16 * u][j];
#pragma unroll
            for (int c = 0; c < 4; c++) vv[c] = vs[j][tx + 16 * c];
#pragma unroll
            for (int u = 0; u < 4; u++)
#pragma unroll
                for (int c = 0; c < 4; c++) acc[u][c] += pv[u] * vv[c];
        }
        __syncthreads();
    }

    float* pvb = &g_pvpart[((size_t)bh * NCH_ + ch) * M_ * DH_];
#pragma unroll
    for (int u = 0; u < 4; u++) {
        int i = ty + 16 * u;
#pragma unroll
        for (int c = 0; c < 4; c++) pvb[i * DH_ + tx + 16 * c] = acc[u][c];
    }
    if (tid < 64) g_denpart[(bh * NCH_ + ch) * M_ + tid] = denloc;

    if (tid < 64) lred[tid] = lossloc;
    __syncthreads();
    if (tid < 32) lred[tid] += lred[tid + 32];
    __syncthreads();
    if (tid == 0) {
        float s = 0.f;
#pragma unroll
        for (int t = 0; t < 32; t++) s += lred[t];
        g_losschunk[bh * NCH_ + ch] = s;
    }
}

// ==================== pv combine ==========================================
__global__ __launch_bounds__(256) void pv_combine_kernel()
{
    const int bh = blockIdx.x;
    const int b  = bh >> 4;
    const int h  = bh & 15;
    const int tid = threadIdx.x;

    __shared__ float dinv[64];
    if (tid < 64) {
        float d = 0.f;
#pragma unroll
        for (int c = 0; c < NCH_; c++) d += g_denpart[(bh * NCH_ + c) * M_ + tid];
        dinv[tid] = 1.0f / d;
    }
    if (tid == 64) {
        float s = 0.f;
#pragma unroll
        for (int c = 0; c < NCH_; c++) s += g_losschunk[bh * NCH_ + c];
        g_losspart[bh] = s;
    }
    __syncthreads();

    const float* pvb = &g_pvpart[(size_t)bh * NCH_ * M_ * DH_];
    for (int idx = tid; idx < M_ * DH_; idx += 256) {
        int i = idx >> 6, d = idx & 63;
        float s = 0.f;
#pragma unroll
        for (int c = 0; c < NCH_; c++) s += pvb[c * M_ * DH_ + idx];
        g_attnout[((size_t)b * M_ + i) * INNER_ + h * DH_ + d] = s * dinv[i];
    }
}

__global__ __launch_bounds__(128) void loss_final_kernel(float* __restrict__ out, int idx)
{
    __shared__ float red[128];
    red[threadIdx.x] = g_losspart[threadIdx.x];
    __syncthreads();
    for (int t = 64; t > 0; t >>= 1) {
        if (threadIdx.x < t) red[threadIdx.x] += red[threadIdx.x + t];
        __syncthreads();
    }
    if (threadIdx.x == 0) out[idx] = red[0] * (1.0f / (float)(B_ * H_ * N_));
}

// ==================== launch ==============================================
extern "C" void kernel_launch(void* const* d_in, const int* in_sizes, int n_in,
                              void* d_out, int out_size)
{
    const float* x       = (const float*)d_in[0];
    const float* latents = (const float*)d_in[1];
    const int*   mask    = (const int*)d_in[2];
    const float* Wq      = (const float*)d_in[3];
    const float* Wkv     = (const float*)d_in[4];
    const float* Wout    = (const float*)d_in[5];
    float*       out     = (float*)d_out;

    cudaFuncSetAttribute(gemm16_kernel, cudaFuncAttributeMaxDynamicSharedMemorySize, GSMEM_B);

    void *pxh, *pxl, *pkvh, *pqh, *poh, *plh, *pll, *pah, *pal;
    void *pq, *pattn, *pkv, *pkv16, *pqh16, *pql16;
    cudaGetSymbolAddress(&pxh, g_xh);   cudaGetSymbolAddress(&pxl, g_xl);
    cudaGetSymbolAddress(&pkvh, g_wkvh);
    cudaGetSymbolAddress(&pqh, g_wqh);  cudaGetSymbolAddress(&poh, g_wouth);
    cudaGetSymbolAddress(&plh, g_lath); cudaGetSymbolAddress(&pll, g_latl);
    cudaGetSymbolAddress(&pah, g_ah);   cudaGetSymbolAddress(&pal, g_al);
    cudaGetSymbolAddress(&pq, g_q);
    cudaGetSymbolAddress(&pkv, g_kv);
    cudaGetSymbolAddress(&pkv16, g_kvh16);
    cudaGetSymbolAddress(&pqh16, g_qh16);
    cudaGetSymbolAddress(&pql16, g_ql16);
    cudaGetSymbolAddress(&pattn, g_attnout);

    // L1: split x -> fp16 hi/lo
    split2_kernel<<<(B_ * N_ * DIM_ / 4 + 255) / 256, 256>>>(
        x, (__half*)pxh, (__half*)pxl, B_ * N_ * DIM_ / 4);

    // L2: split weights + latents, init rmax/loss
    prep_kernel<<<(PR_END + 255) / 256, 256>>>(Wkv, Wq, Wout, latents);

    // L3: q = latents @ Wq^T * scale
    gemm16_kernel<<<dim3(INNER_ / 128, (B_ * M_) / 128), 256, GSMEM_B>>>(
        (const __half*)plh, (const __half*)pll, (const __half*)pqh,
        (float*)pq, nullptr, INNER_, DIM_, 0.125f);

    // L4: kv = x @ Wkv^T  (+ fp16 copy)   (profiled launch)
    gemm16_kernel<<<dim3(KV2_ / 128, (B_ * N_) / 128), 256, GSMEM_B>>>(
        (const __half*)pxh, (const __half*)pxl, (const __half*)pkvh,
        (float*)pkv, (__half*)pkv16, KV2_, DIM_, 1.0f);

    // L5: split q -> fp16 hi/lo for sim
    split2_kernel<<<(B_ * M_ * INNER_ / 4 + 255) / 256, 256>>>(
        (const float*)pq, (__half*)pqh16, (__half*)pql16, B_ * M_ * INNER_ / 4);

    // L6: sim via tensor cores (mask + rowmax fused)
    sim_mma_kernel<<<dim3(N_ / 128, B_ * H_), 256>>>(mask);

    // L7: pv chunks
    pv_chunk_kernel<<<dim3(NCH_, B_ * H_), 256>>>(mask);

    // L8: combine
    pv_combine_kernel<<<B_ * H_, 256>>>();

    // L9: split attn output
    split2_kernel<<<(B_ * M_ * INNER_ / 4 + 255) / 256, 256>>>(
        (const float*)pattn, (__half*)pah, (__half*)pal, B_ * M_ * INNER_ / 4);

    // L10: loss finalize
    loss_final_kernel<<<1, 128>>>(out, out_size - 1);

    // L11: out = attn_out @ Wout^T
    gemm16_kernel<<<dim3(DIM_ / 128, (B_ * M_) / 128), 256, GSMEM_B>>>(
        (const __half*)pah, (const __half*)pal, (const __half*)poh,
        out, nullptr, DIM_, INNER_, 1.0f);
}